// round 1
// baseline (speedup 1.0000x reference)
#include <cuda_runtime.h>
#include <stdint.h>

// ---------------- problem constants ----------------
#define NB   2
#define TT   2048            // seq len
#define DM   2048            // d_model
#define NH   16
#define HD   128
#define DFF  8192
#define TOK  (NB*TT)         // 4096 tokens

// ---------------- scratch (device globals; no allocs allowed) ----------------
__device__ float g_h1  [(size_t)TOK*DM];
__device__ float g_q   [(size_t)TOK*DM];
__device__ float g_k   [(size_t)TOK*DM];
__device__ float g_v   [(size_t)TOK*DM];
__device__ float g_vT  [(size_t)TOK*DM];
__device__ float g_sc  [(size_t)NB*NH*TT*TT];   // 512 MB scores / probs (in-place softmax)
__device__ float g_attn[(size_t)TOK*DM];
__device__ float g_x1  [(size_t)TOK*DM];
__device__ float g_h2  [(size_t)TOK*DM];
__device__ float g_gate[(size_t)TOK*DFF];
__device__ float g_up  [(size_t)TOK*DFF];
__device__ float g_ff  [(size_t)TOK*DFF];

// ---------------- helpers ----------------
__device__ __forceinline__ uint32_t f2tf32(float f) {
    uint32_t r;
    asm("cvt.rna.tf32.f32 %0, %1;" : "=r"(r) : "f"(f));
    return r;
}

__device__ __forceinline__ void cpasync16(void* dst, const void* src) {
    uint32_t s = (uint32_t)__cvta_generic_to_shared(dst);
    asm volatile("cp.async.cg.shared.global [%0], [%1], 16;\n" :: "r"(s), "l"(src));
}

// ---------------- generic TF32 GEMM ----------------
// C[m,n] = scale * sum_k A[m,k] * B[n,k]   (+ Res[m,n] if epi==1)
// A: [M,K] lda, B: [N,K] ldb (both K-major), C: [M,N] ldc.
// Batched via blockIdx.z: off = (z/zdiv)*hi + (z%zdiv)*lo per operand.
#define BM  128
#define BN  128
#define BK  16
#define BKP 20   // +4 float pad -> conflict-free fragment loads

__global__ __launch_bounds__(256)
void gemm_tf32_kernel(const float* __restrict__ A, const float* __restrict__ Bm,
                      float* __restrict__ C, const float* __restrict__ Res,
                      int K, int lda, int ldb, int ldc,
                      long long zaLo, long long zaHi,
                      long long zbLo, long long zbHi,
                      long long zcLo, long long zcHi,
                      int zdiv, float scale, int epi)
{
    long long zq = blockIdx.z / zdiv, zr = blockIdx.z % zdiv;
    A  += zq*zaHi + zr*zaLo;
    Bm += zq*zbHi + zr*zbLo;
    C  += zq*zcHi + zr*zcLo;
    if (epi == 1) Res += zq*zcHi + zr*zcLo;

    const int m0 = blockIdx.y * BM;
    const int n0 = blockIdx.x * BN;

    __shared__ float sA[2][BM*BKP];
    __shared__ float sB[2][BN*BKP];

    const int tid  = threadIdx.x;
    const int lane = tid & 31;
    const int warp = tid >> 5;
    const int mb   = (warp & 3) * 32;   // warp tile 32(M) x 64(N)
    const int nb   = (warp >> 2) * 64;

    float acc[2][8][4];
#pragma unroll
    for (int i = 0; i < 2; i++)
#pragma unroll
        for (int j = 0; j < 8; j++)
#pragma unroll
            for (int l = 0; l < 4; l++) acc[i][j][l] = 0.f;

    const int nK = K / BK;

    auto load_stage = [&](int st, int kt) {
        const int k0 = kt * BK;
#pragma unroll
        for (int i = 0; i < 2; i++) {
            int idx = tid + i * 256;          // 0..511
            int row = idx >> 2;               // 0..127
            int c4  = (idx & 3) << 2;         // 0,4,8,12
            cpasync16(&sA[st][row*BKP + c4], A + (size_t)(m0+row)*lda + k0 + c4);
        }
#pragma unroll
        for (int i = 0; i < 2; i++) {
            int idx = tid + i * 256;
            int row = idx >> 2;
            int c4  = (idx & 3) << 2;
            cpasync16(&sB[st][row*BKP + c4], Bm + (size_t)(n0+row)*ldb + k0 + c4);
        }
    };

    load_stage(0, 0);
    asm volatile("cp.async.commit_group;\n");

    for (int kt = 0; kt < nK; kt++) {
        const int st = kt & 1;
        if (kt + 1 < nK) {
            load_stage(st ^ 1, kt + 1);
            asm volatile("cp.async.commit_group;\n");
            asm volatile("cp.async.wait_group 1;\n");
        } else {
            asm volatile("cp.async.wait_group 0;\n");
        }
        __syncthreads();

        const float* As = sA[st];
        const float* Bs = sB[st];
#pragma unroll
        for (int kk = 0; kk < BK; kk += 8) {
            uint32_t af[2][4];
#pragma unroll
            for (int im = 0; im < 2; im++) {
                int r = mb + im*16 + (lane >> 2);
                int c = kk + (lane & 3);
                af[im][0] = f2tf32(As[(r  )*BKP + c    ]);
                af[im][1] = f2tf32(As[(r+8)*BKP + c    ]);
                af[im][2] = f2tf32(As[(r  )*BKP + c + 4]);
                af[im][3] = f2tf32(As[(r+8)*BKP + c + 4]);
            }
            uint32_t bf[8][2];
#pragma unroll
            for (int in = 0; in < 8; in++) {
                int n = nb + in*8 + (lane >> 2);
                int c = kk + (lane & 3);
                bf[in][0] = f2tf32(Bs[n*BKP + c    ]);
                bf[in][1] = f2tf32(Bs[n*BKP + c + 4]);
            }
#pragma unroll
            for (int im = 0; im < 2; im++)
#pragma unroll
                for (int in = 0; in < 8; in++) {
                    asm volatile(
                        "mma.sync.aligned.m16n8k8.row.col.f32.tf32.tf32.f32 "
                        "{%0,%1,%2,%3}, {%4,%5,%6,%7}, {%8,%9}, {%0,%1,%2,%3};\n"
                        : "+f"(acc[im][in][0]), "+f"(acc[im][in][1]),
                          "+f"(acc[im][in][2]), "+f"(acc[im][in][3])
                        : "r"(af[im][0]), "r"(af[im][1]),
                          "r"(af[im][2]), "r"(af[im][3]),
                          "r"(bf[in][0]), "r"(bf[in][1]));
                }
        }
        __syncthreads();
    }

    // epilogue
#pragma unroll
    for (int im = 0; im < 2; im++) {
#pragma unroll
        for (int in = 0; in < 8; in++) {
            int r = m0 + mb + im*16 + (lane >> 2);
            int c = n0 + nb + in*8 + ((lane & 3) << 1);
            float v0 = acc[im][in][0] * scale;
            float v1 = acc[im][in][1] * scale;
            float v2 = acc[im][in][2] * scale;
            float v3 = acc[im][in][3] * scale;
            if (epi == 1) {
                v0 += Res[(size_t)(r  )*ldc + c    ];
                v1 += Res[(size_t)(r  )*ldc + c + 1];
                v2 += Res[(size_t)(r+8)*ldc + c    ];
                v3 += Res[(size_t)(r+8)*ldc + c + 1];
            }
            C[(size_t)(r  )*ldc + c    ] = v0;
            C[(size_t)(r  )*ldc + c + 1] = v1;
            C[(size_t)(r+8)*ldc + c    ] = v2;
            C[(size_t)(r+8)*ldc + c + 1] = v3;
        }
    }
}

// ---------------- LayerNorm ----------------
__global__ __launch_bounds__(256)
void ln_kernel(const float* __restrict__ x, const float* __restrict__ w,
               const float* __restrict__ b, float* __restrict__ y)
{
    const int row = blockIdx.x;
    const float* xr = x + (size_t)row * DM;
    float*       yr = y + (size_t)row * DM;

    float s = 0.f, sq = 0.f;
#pragma unroll
    for (int i = 0; i < DM/256; i++) {
        float v = xr[threadIdx.x + i*256];
        s += v; sq += v*v;
    }
#pragma unroll
    for (int o = 16; o; o >>= 1) {
        s  += __shfl_xor_sync(0xffffffffu, s,  o);
        sq += __shfl_xor_sync(0xffffffffu, sq, o);
    }
    __shared__ float sh[64];
    const int warp = threadIdx.x >> 5, lane = threadIdx.x & 31;
    if (lane == 0) { sh[warp] = s; sh[warp + 32] = sq; }
    __syncthreads();
    if (warp == 0) {
        s  = (lane < 8) ? sh[lane]      : 0.f;
        sq = (lane < 8) ? sh[lane + 32] : 0.f;
#pragma unroll
        for (int o = 4; o; o >>= 1) {
            s  += __shfl_xor_sync(0xffffffffu, s,  o);
            sq += __shfl_xor_sync(0xffffffffu, sq, o);
        }
        if (lane == 0) { sh[0] = s; sh[1] = sq; }
    }
    __syncthreads();
    const float mean = sh[0] * (1.f/DM);
    const float var  = sh[1] * (1.f/DM) - mean*mean;
    const float inv  = rsqrtf(var + 1e-5f);
#pragma unroll
    for (int i = 0; i < DM/256; i++) {
        int c = threadIdx.x + i*256;
        yr[c] = (xr[c] - mean) * inv * w[c] + b[c];
    }
}

// ---------------- softmax (in place, rows of TT) ----------------
__global__ __launch_bounds__(256)
void softmax_kernel(float* __restrict__ s)
{
    float* r = s + (size_t)blockIdx.x * TT;
    float v[TT/256];
    float mx = -1e30f;
#pragma unroll
    for (int i = 0; i < TT/256; i++) {
        v[i] = r[threadIdx.x + i*256];
        mx = fmaxf(mx, v[i]);
    }
#pragma unroll
    for (int o = 16; o; o >>= 1) mx = fmaxf(mx, __shfl_xor_sync(0xffffffffu, mx, o));
    __shared__ float sh[32];
    const int warp = threadIdx.x >> 5, lane = threadIdx.x & 31;
    if (lane == 0) sh[warp] = mx;
    __syncthreads();
    if (warp == 0) {
        mx = (lane < 8) ? sh[lane] : -1e30f;
#pragma unroll
        for (int o = 4; o; o >>= 1) mx = fmaxf(mx, __shfl_xor_sync(0xffffffffu, mx, o));
        if (lane == 0) sh[0] = mx;
    }
    __syncthreads();
    mx = sh[0];

    float sum = 0.f;
#pragma unroll
    for (int i = 0; i < TT/256; i++) { v[i] = __expf(v[i] - mx); sum += v[i]; }
#pragma unroll
    for (int o = 16; o; o >>= 1) sum += __shfl_xor_sync(0xffffffffu, sum, o);
    if (lane == 0) sh[warp] = sum;
    __syncthreads();
    if (warp == 0) {
        sum = (lane < 8) ? sh[lane] : 0.f;
#pragma unroll
        for (int o = 4; o; o >>= 1) sum += __shfl_xor_sync(0xffffffffu, sum, o);
        if (lane == 0) sh[0] = sum;
    }
    __syncthreads();
    const float inv = 1.f / sh[0];
#pragma unroll
    for (int i = 0; i < TT/256; i++) r[threadIdx.x + i*256] = v[i] * inv;
}

// ---------------- per-batch 2048x2048 transpose (V -> V^T) ----------------
__global__ void transpose_v_kernel(const float* __restrict__ v, float* __restrict__ vt)
{
    __shared__ float tile[32][33];
    const int b  = blockIdx.z;
    const int x0 = blockIdx.x * 32;   // column in v
    const int y0 = blockIdx.y * 32;   // row (t) in v
    const float* vb = v  + (size_t)b * TT * DM;
    float*      vtb = vt + (size_t)b * TT * DM;
    const int tx = threadIdx.x, ty = threadIdx.y;   // 32 x 8
#pragma unroll
    for (int i = 0; i < 32; i += 8)
        tile[ty + i][tx] = vb[(size_t)(y0 + ty + i) * DM + x0 + tx];
    __syncthreads();
#pragma unroll
    for (int i = 0; i < 32; i += 8)
        vtb[(size_t)(x0 + ty + i) * TT + y0 + tx] = tile[tx][ty + i];
}

// ---------------- SwiGLU ----------------
__global__ __launch_bounds__(256)
void swiglu_kernel(const float* __restrict__ g, const float* __restrict__ u,
                   float* __restrict__ o)
{
    size_t i = (size_t)blockIdx.x * 256 + threadIdx.x;
    float x = g[i];
    o[i] = (x / (1.f + __expf(-x))) * u[i];
}

// ---------------- launch ----------------
extern "C" void kernel_launch(void* const* d_in, const int* in_sizes, int n_in,
                              void* d_out, int out_size)
{
    const float* x     = (const float*)d_in[0];
    const float* wq    = (const float*)d_in[1];
    const float* wk    = (const float*)d_in[2];
    const float* wv    = (const float*)d_in[3];
    const float* wo    = (const float*)d_in[4];
    const float* wg    = (const float*)d_in[5];
    const float* wu    = (const float*)d_in[6];
    const float* wd    = (const float*)d_in[7];
    const float* ln1w  = (const float*)d_in[8];
    const float* ln1b  = (const float*)d_in[9];
    const float* ln2w  = (const float*)d_in[10];
    const float* ln2b  = (const float*)d_in[11];
    float* out = (float*)d_out;

    float *h1, *q, *k, *v, *vt, *sc, *attn, *x1, *h2, *gate, *up, *ff;
    cudaGetSymbolAddress((void**)&h1,   g_h1);
    cudaGetSymbolAddress((void**)&q,    g_q);
    cudaGetSymbolAddress((void**)&k,    g_k);
    cudaGetSymbolAddress((void**)&v,    g_v);
    cudaGetSymbolAddress((void**)&vt,   g_vT);
    cudaGetSymbolAddress((void**)&sc,   g_sc);
    cudaGetSymbolAddress((void**)&attn, g_attn);
    cudaGetSymbolAddress((void**)&x1,   g_x1);
    cudaGetSymbolAddress((void**)&h2,   g_h2);
    cudaGetSymbolAddress((void**)&gate, g_gate);
    cudaGetSymbolAddress((void**)&up,   g_up);
    cudaGetSymbolAddress((void**)&ff,   g_ff);

    const long long LTTDM = (long long)TT * DM;    // 2048*2048
    const long long LTTTT = (long long)TT * TT;

    // 1. h1 = LN1(x)
    ln_kernel<<<TOK, 256>>>(x, ln1w, ln1b, h1);

    // 2-4. q, k, v projections  [4096,2048] x [2048,2048]^T
    {
        dim3 grid(DM/BN, TOK/BM, 1);
        gemm_tf32_kernel<<<grid, 256>>>(h1, wq, q, nullptr, DM, DM, DM, DM,
                                        0,0, 0,0, 0,0, 1, 1.f, 0);
        gemm_tf32_kernel<<<grid, 256>>>(h1, wk, k, nullptr, DM, DM, DM, DM,
                                        0,0, 0,0, 0,0, 1, 1.f, 0);
        gemm_tf32_kernel<<<grid, 256>>>(h1, wv, v, nullptr, DM, DM, DM, DM,
                                        0,0, 0,0, 0,0, 1, 1.f, 0);
    }

    // 5. V^T per batch
    {
        dim3 grid(DM/32, TT/32, NB);
        dim3 blk(32, 8);
        transpose_v_kernel<<<grid, blk>>>(v, vt);
    }

    // 6. scores = Q @ K^T / sqrt(HD), batched over (b,h): z = b*16 + h
    {
        dim3 grid(TT/BN, TT/BM, NB*NH);
        gemm_tf32_kernel<<<grid, 256>>>(q, k, sc, nullptr, HD, DM, DM, TT,
                                        (long long)HD, LTTDM,     // A: +h*128, +b*T*DM
                                        (long long)HD, LTTDM,     // B: same
                                        LTTTT, 16*LTTTT,          // C: +bh*T*T
                                        NH, 0.08838834764831845f, 0);
    }

    // 7. softmax rows (in place)
    softmax_kernel<<<NB*NH*TT, 256>>>(sc);

    // 8. attn_out = P @ V  (B = V^T slice [HD, TT] K-major)
    {
        dim3 grid(HD/BN, TT/BM, NB*NH);
        gemm_tf32_kernel<<<grid, 256>>>(sc, vt, attn, nullptr, TT, TT, TT, DM,
                                        LTTTT, 16*LTTTT,               // A: probs
                                        (long long)HD*TT, LTTDM,       // B: vT
                                        (long long)HD, LTTDM,          // C: attn cols h*128
                                        NH, 1.f, 0);
    }

    // 9. x1 = x + attn_out @ wo^T
    {
        dim3 grid(DM/BN, TOK/BM, 1);
        gemm_tf32_kernel<<<grid, 256>>>(attn, wo, x1, x, DM, DM, DM, DM,
                                        0,0, 0,0, 0,0, 1, 1.f, 1);
    }

    // 10. h2 = LN2(x1)
    ln_kernel<<<TOK, 256>>>(x1, ln2w, ln2b, h2);

    // 11-12. gate / up  [4096,2048] x [8192,2048]^T
    {
        dim3 grid(DFF/BN, TOK/BM, 1);
        gemm_tf32_kernel<<<grid, 256>>>(h2, wg, gate, nullptr, DM, DM, DM, DFF,
                                        0,0, 0,0, 0,0, 1, 1.f, 0);
        gemm_tf32_kernel<<<grid, 256>>>(h2, wu, up, nullptr, DM, DM, DM, DFF,
                                        0,0, 0,0, 0,0, 1, 1.f, 0);
    }

    // 13. ff = silu(gate) * up
    swiglu_kernel<<<(unsigned)((size_t)TOK*DFF/256), 256>>>(gate, up, ff);

    // 14. out = x1 + ff @ wd^T   [4096,8192] x [2048,8192]^T
    {
        dim3 grid(DM/BN, TOK/BM, 1);
        gemm_tf32_kernel<<<grid, 256>>>(ff, wd, out, x1, DFF, DFF, DFF, DM,
                                        0,0, 0,0, 0,0, 1, 1.f, 1);
    }
}

// round 3
// speedup vs baseline: 1.1420x; 1.1420x over previous
#include <cuda_runtime.h>
#include <stdint.h>

// ---------------- problem constants ----------------
#define NB   2
#define TT   2048            // seq len
#define DM   2048            // d_model
#define NH   16
#define HD   128
#define DFF  8192
#define TOK  (NB*TT)         // 4096 tokens

// ---------------- scratch (device globals; no allocs allowed) ----------------
__device__ float g_h1  [(size_t)TOK*DM];
__device__ float g_q   [(size_t)TOK*DM];
__device__ float g_k   [(size_t)TOK*DM];
__device__ float g_v   [(size_t)TOK*DM];
__device__ float g_vT  [(size_t)TOK*DM];
__device__ float g_sc  [(size_t)NB*NH*TT*TT];   // 512 MB scores / probs
__device__ float g_attn[(size_t)TOK*DM];
__device__ float g_x1  [(size_t)TOK*DM];
__device__ float g_h2  [(size_t)TOK*DM];
__device__ float g_gate[(size_t)TOK*DFF];
__device__ float g_up  [(size_t)TOK*DFF];
__device__ float g_ff  [(size_t)TOK*DFF];
// tf32-rounded weight copies
__device__ float g_wq[(size_t)DM*DM];
__device__ float g_wk[(size_t)DM*DM];
__device__ float g_wv[(size_t)DM*DM];
__device__ float g_wo[(size_t)DM*DM];
__device__ float g_wg[(size_t)DFF*DM];
__device__ float g_wu[(size_t)DFF*DM];
__device__ float g_wd[(size_t)DM*DFF];

// ---------------- helpers ----------------
__device__ __forceinline__ float tf32r(float f) {
    uint32_t r;
    asm("cvt.rna.tf32.f32 %0, %1;" : "=r"(r) : "f"(f));
    return __uint_as_float(r);
}

__device__ __forceinline__ void cpasync16(void* dst, const void* src) {
    uint32_t s = (uint32_t)__cvta_generic_to_shared(dst);
    asm volatile("cp.async.cg.shared.global [%0], [%1], 16;\n" :: "r"(s), "l"(src));
}

// ---------------- generic TF32 GEMM (inputs pre-rounded to tf32 pattern) -----
// C[m,n] = scale * sum_k A[m,k] * B[n,k]   (+ Res[m,n] if epi==1)
// optional roundC: round output to tf32 pattern (for tensors feeding later mma)
#define BM  128
#define BN  128
#define BK  32
#define BKP 36           // +4 float pad -> conflict-free fragment loads
#define STAGE_F (BM*BKP) // floats per stage (A or B): 4608
#define NSTAGE 3
#define GEMM_SMEM_BYTES (2*NSTAGE*STAGE_F*4)   // 110,592 B

extern __shared__ float g_smem[];

__global__ __launch_bounds__(256, 2)
void gemm_tf32_kernel(const float* __restrict__ A, const float* __restrict__ Bm,
                      float* __restrict__ C, const float* __restrict__ Res,
                      int K, int lda, int ldb, int ldc,
                      long long zaLo, long long zaHi,
                      long long zbLo, long long zbHi,
                      long long zcLo, long long zcHi,
                      int zdiv, float scale, int epi, int roundC)
{
    long long zq = blockIdx.z / zdiv, zr = blockIdx.z % zdiv;
    A  += zq*zaHi + zr*zaLo;
    Bm += zq*zbHi + zr*zbLo;
    C  += zq*zcHi + zr*zcLo;
    if (epi == 1) Res += zq*zcHi + zr*zcLo;

    const int m0 = blockIdx.y * BM;
    const int n0 = blockIdx.x * BN;

    float* sm_a = g_smem;
    float* sm_b = g_smem + NSTAGE*STAGE_F;

    const int tid  = threadIdx.x;
    const int lane = tid & 31;
    const int warp = tid >> 5;
    const int mb   = (warp & 3) * 32;   // warp tile 32(M) x 64(N)
    const int nb   = (warp >> 2) * 64;

    float acc[2][8][4];
#pragma unroll
    for (int i = 0; i < 2; i++)
#pragma unroll
        for (int j = 0; j < 8; j++)
#pragma unroll
            for (int l = 0; l < 4; l++) acc[i][j][l] = 0.f;

    const int nK = K / BK;

    auto load_stage = [&](int st, int kt) {
        const int k0 = kt * BK;
        float* sa = sm_a + st*STAGE_F;
        float* sb = sm_b + st*STAGE_F;
#pragma unroll
        for (int i = 0; i < 4; i++) {
            int idx = tid + i * 256;          // 0..1023
            int row = idx >> 3;               // 0..127
            int c4  = (idx & 7) << 2;         // 0..28 step 4
            cpasync16(&sa[row*BKP + c4], A + (size_t)(m0+row)*lda + k0 + c4);
        }
#pragma unroll
        for (int i = 0; i < 4; i++) {
            int idx = tid + i * 256;
            int row = idx >> 3;
            int c4  = (idx & 7) << 2;
            cpasync16(&sb[row*BKP + c4], Bm + (size_t)(n0+row)*ldb + k0 + c4);
        }
    };

    // prologue: 2 tiles in flight (nK >= 4 for all our shapes)
    load_stage(0, 0);
    asm volatile("cp.async.commit_group;\n");
    load_stage(1, 1);
    asm volatile("cp.async.commit_group;\n");

    for (int kt = 0; kt < nK; kt++) {
        asm volatile("cp.async.wait_group 1;\n");
        __syncthreads();

        if (kt + 2 < nK) load_stage((kt + 2) % NSTAGE, kt + 2);
        asm volatile("cp.async.commit_group;\n");

        const float* As = sm_a + (kt % NSTAGE)*STAGE_F;
        const float* Bs = sm_b + (kt % NSTAGE)*STAGE_F;
#pragma unroll
        for (int kk = 0; kk < BK; kk += 8) {
            uint32_t af[2][4];
#pragma unroll
            for (int im = 0; im < 2; im++) {
                int r = mb + im*16 + (lane >> 2);
                int c = kk + (lane & 3);
                af[im][0] = __float_as_uint(As[(r  )*BKP + c    ]);
                af[im][1] = __float_as_uint(As[(r+8)*BKP + c    ]);
                af[im][2] = __float_as_uint(As[(r  )*BKP + c + 4]);
                af[im][3] = __float_as_uint(As[(r+8)*BKP + c + 4]);
            }
            uint32_t bf[8][2];
#pragma unroll
            for (int in = 0; in < 8; in++) {
                int n = nb + in*8 + (lane >> 2);
                int c = kk + (lane & 3);
                bf[in][0] = __float_as_uint(Bs[n*BKP + c    ]);
                bf[in][1] = __float_as_uint(Bs[n*BKP + c + 4]);
            }
#pragma unroll
            for (int im = 0; im < 2; im++)
#pragma unroll
                for (int in = 0; in < 8; in++) {
                    asm volatile(
                        "mma.sync.aligned.m16n8k8.row.col.f32.tf32.tf32.f32 "
                        "{%0,%1,%2,%3}, {%4,%5,%6,%7}, {%8,%9}, {%0,%1,%2,%3};\n"
                        : "+f"(acc[im][in][0]), "+f"(acc[im][in][1]),
                          "+f"(acc[im][in][2]), "+f"(acc[im][in][3])
                        : "r"(af[im][0]), "r"(af[im][1]),
                          "r"(af[im][2]), "r"(af[im][3]),
                          "r"(bf[in][0]), "r"(bf[in][1]));
                }
        }
        __syncthreads();
    }

    // epilogue (float2 stores)
#pragma unroll
    for (int im = 0; im < 2; im++) {
#pragma unroll
        for (int in = 0; in < 8; in++) {
            int r = m0 + mb + im*16 + (lane >> 2);
            int c = n0 + nb + in*8 + ((lane & 3) << 1);
            float2 t0, t1;
            t0.x = acc[im][in][0] * scale;
            t0.y = acc[im][in][1] * scale;
            t1.x = acc[im][in][2] * scale;
            t1.y = acc[im][in][3] * scale;
            if (epi == 1) {
                float2 r0 = *(const float2*)&Res[(size_t)(r  )*ldc + c];
                float2 r1 = *(const float2*)&Res[(size_t)(r+8)*ldc + c];
                t0.x += r0.x; t0.y += r0.y;
                t1.x += r1.x; t1.y += r1.y;
            }
            if (roundC) {
                t0.x = tf32r(t0.x); t0.y = tf32r(t0.y);
                t1.x = tf32r(t1.x); t1.y = tf32r(t1.y);
            }
            *(float2*)&C[(size_t)(r  )*ldc + c] = t0;
            *(float2*)&C[(size_t)(r+8)*ldc + c] = t1;
        }
    }
}

// ---------------- weight rounding (f32 -> tf32 bit pattern) ----------------
__global__ __launch_bounds__(256)
void round_kernel(const float* __restrict__ in, float* __restrict__ out, int n4)
{
    int i = blockIdx.x * 256 + threadIdx.x;
    if (i < n4) {
        float4 v = ((const float4*)in)[i];
        v.x = tf32r(v.x); v.y = tf32r(v.y);
        v.z = tf32r(v.z); v.w = tf32r(v.w);
        ((float4*)out)[i] = v;
    }
}

// ---------------- LayerNorm (output tf32-rounded) ----------------
__global__ __launch_bounds__(256)
void ln_kernel(const float* __restrict__ x, const float* __restrict__ w,
               const float* __restrict__ b, float* __restrict__ y)
{
    const int row = blockIdx.x;
    const float* xr = x + (size_t)row * DM;
    float*       yr = y + (size_t)row * DM;

    float s = 0.f, sq = 0.f;
#pragma unroll
    for (int i = 0; i < DM/256; i++) {
        float v = xr[threadIdx.x + i*256];
        s += v; sq += v*v;
    }
#pragma unroll
    for (int o = 16; o; o >>= 1) {
        s  += __shfl_xor_sync(0xffffffffu, s,  o);
        sq += __shfl_xor_sync(0xffffffffu, sq, o);
    }
    __shared__ float sh[64];
    const int warp = threadIdx.x >> 5, lane = threadIdx.x & 31;
    if (lane == 0) { sh[warp] = s; sh[warp + 32] = sq; }
    __syncthreads();
    if (warp == 0) {
        s  = (lane < 8) ? sh[lane]      : 0.f;
        sq = (lane < 8) ? sh[lane + 32] : 0.f;
#pragma unroll
        for (int o = 4; o; o >>= 1) {
            s  += __shfl_xor_sync(0xffffffffu, s,  o);
            sq += __shfl_xor_sync(0xffffffffu, sq, o);
        }
        if (lane == 0) { sh[0] = s; sh[1] = sq; }
    }
    __syncthreads();
    const float mean = sh[0] * (1.f/DM);
    const float var  = sh[1] * (1.f/DM) - mean*mean;
    const float inv  = rsqrtf(var + 1e-5f);
#pragma unroll
    for (int i = 0; i < DM/256; i++) {
        int c = threadIdx.x + i*256;
        yr[c] = tf32r((xr[c] - mean) * inv * w[c] + b[c]);
    }
}

// ---------------- softmax (in place, rows of TT; output rounded) -----------
__global__ __launch_bounds__(256)
void softmax_kernel(float* __restrict__ s)
{
    float* r = s + (size_t)blockIdx.x * TT;
    float v[TT/256];
    float mx = -1e30f;
#pragma unroll
    for (int i = 0; i < TT/256; i++) {
        v[i] = r[threadIdx.x + i*256];
        mx = fmaxf(mx, v[i]);
    }
#pragma unroll
    for (int o = 16; o; o >>= 1) mx = fmaxf(mx, __shfl_xor_sync(0xffffffffu, mx, o));
    __shared__ float sh[32];
    const int warp = threadIdx.x >> 5, lane = threadIdx.x & 31;
    if (lane == 0) sh[warp] = mx;
    __syncthreads();
    if (warp == 0) {
        mx = (lane < 8) ? sh[lane] : -1e30f;
#pragma unroll
        for (int o = 4; o; o >>= 1) mx = fmaxf(mx, __shfl_xor_sync(0xffffffffu, mx, o));
        if (lane == 0) sh[0] = mx;
    }
    __syncthreads();
    mx = sh[0];

    float sum = 0.f;
#pragma unroll
    for (int i = 0; i < TT/256; i++) { v[i] = __expf(v[i] - mx); sum += v[i]; }
#pragma unroll
    for (int o = 16; o; o >>= 1) sum += __shfl_xor_sync(0xffffffffu, sum, o);
    if (lane == 0) sh[warp] = sum;
    __syncthreads();
    if (warp == 0) {
        sum = (lane < 8) ? sh[lane] : 0.f;
#pragma unroll
        for (int o = 4; o; o >>= 1) sum += __shfl_xor_sync(0xffffffffu, sum, o);
        if (lane == 0) sh[0] = sum;
    }
    __syncthreads();
    const float inv = 1.f / sh[0];
#pragma unroll
    for (int i = 0; i < TT/256; i++) r[threadIdx.x + i*256] = tf32r(v[i] * inv);
}

// ---------------- per-batch 2048x2048 transpose (V -> V^T) ----------------
__global__ void transpose_v_kernel(const float* __restrict__ v, float* __restrict__ vt)
{
    __shared__ float tile[32][33];
    const int b  = blockIdx.z;
    const int x0 = blockIdx.x * 32;
    const int y0 = blockIdx.y * 32;
    const float* vb = v  + (size_t)b * TT * DM;
    float*      vtb = vt + (size_t)b * TT * DM;
    const int tx = threadIdx.x, ty = threadIdx.y;   // 32 x 8
#pragma unroll
    for (int i = 0; i < 32; i += 8)
        tile[ty + i][tx] = vb[(size_t)(y0 + ty + i) * DM + x0 + tx];
    __syncthreads();
#pragma unroll
    for (int i = 0; i < 32; i += 8)
        vtb[(size_t)(x0 + ty + i) * TT + y0 + tx] = tile[tx][ty + i];
}

// ---------------- SwiGLU (output rounded) ----------------
__global__ __launch_bounds__(256)
void swiglu_kernel(const float* __restrict__ g, const float* __restrict__ u,
                   float* __restrict__ o)
{
    size_t i = (size_t)blockIdx.x * 256 + threadIdx.x;
    float x = g[i];
    o[i] = tf32r((x / (1.f + __expf(-x))) * u[i]);
}

// ---------------- launch ----------------
extern "C" void kernel_launch(void* const* d_in, const int* in_sizes, int n_in,
                              void* d_out, int out_size)
{
    const float* x     = (const float*)d_in[0];
    const float* wq    = (const float*)d_in[1];
    const float* wk    = (const float*)d_in[2];
    const float* wv    = (const float*)d_in[3];
    const float* wo    = (const float*)d_in[4];
    const float* wg    = (const float*)d_in[5];
    const float* wu    = (const float*)d_in[6];
    const float* wd    = (const float*)d_in[7];
    const float* ln1w  = (const float*)d_in[8];
    const float* ln1b  = (const float*)d_in[9];
    const float* ln2w  = (const float*)d_in[10];
    const float* ln2b  = (const float*)d_in[11];
    float* out = (float*)d_out;

    float *h1, *q, *k, *v, *vt, *sc, *attn, *x1, *h2, *gate, *up, *ff;
    float *rwq, *rwk, *rwv, *rwo, *rwg, *rwu, *rwd;
    cudaGetSymbolAddress((void**)&h1,   g_h1);
    cudaGetSymbolAddress((void**)&q,    g_q);
    cudaGetSymbolAddress((void**)&k,    g_k);
    cudaGetSymbolAddress((void**)&v,    g_v);
    cudaGetSymbolAddress((void**)&vt,   g_vT);
    cudaGetSymbolAddress((void**)&sc,   g_sc);
    cudaGetSymbolAddress((void**)&attn, g_attn);
    cudaGetSymbolAddress((void**)&x1,   g_x1);
    cudaGetSymbolAddress((void**)&h2,   g_h2);
    cudaGetSymbolAddress((void**)&gate, g_gate);
    cudaGetSymbolAddress((void**)&up,   g_up);
    cudaGetSymbolAddress((void**)&ff,   g_ff);
    cudaGetSymbolAddress((void**)&rwq,  g_wq);
    cudaGetSymbolAddress((void**)&rwk,  g_wk);
    cudaGetSymbolAddress((void**)&rwv,  g_wv);
    cudaGetSymbolAddress((void**)&rwo,  g_wo);
    cudaGetSymbolAddress((void**)&rwg,  g_wg);
    cudaGetSymbolAddress((void**)&rwu,  g_wu);
    cudaGetSymbolAddress((void**)&rwd,  g_wd);

    cudaFuncSetAttribute(gemm_tf32_kernel,
                         cudaFuncAttributeMaxDynamicSharedMemorySize,
                         GEMM_SMEM_BYTES);

    const long long LTTDM = (long long)TT * DM;
    const long long LTTTT = (long long)TT * TT;

    // 0. round weights to tf32 pattern
    {
        int n4s = DM*DM/4;    // 1,048,576
        int n4l = DFF*DM/4;   // 4,194,304
        round_kernel<<<(n4s+255)/256, 256>>>(wq, rwq, n4s);
        round_kernel<<<(n4s+255)/256, 256>>>(wk, rwk, n4s);
        round_kernel<<<(n4s+255)/256, 256>>>(wv, rwv, n4s);
        round_kernel<<<(n4s+255)/256, 256>>>(wo, rwo, n4s);
        round_kernel<<<(n4l+255)/256, 256>>>(wg, rwg, n4l);
        round_kernel<<<(n4l+255)/256, 256>>>(wu, rwu, n4l);
        round_kernel<<<(n4l+255)/256, 256>>>(wd, rwd, n4l);
    }

    // 1. h1 = round(LN1(x))
    ln_kernel<<<TOK, 256>>>(x, ln1w, ln1b, h1);

    // 2-4. q, k, v projections (outputs rounded: they feed QK / PV mma)
    {
        dim3 grid(DM/BN, TOK/BM, 1);
        gemm_tf32_kernel<<<grid, 256, GEMM_SMEM_BYTES>>>(h1, rwq, q, nullptr, DM, DM, DM, DM,
                                        0,0, 0,0, 0,0, 1, 1.f, 0, 1);
        gemm_tf32_kernel<<<grid, 256, GEMM_SMEM_BYTES>>>(h1, rwk, k, nullptr, DM, DM, DM, DM,
                                        0,0, 0,0, 0,0, 1, 1.f, 0, 1);
        gemm_tf32_kernel<<<grid, 256, GEMM_SMEM_BYTES>>>(h1, rwv, v, nullptr, DM, DM, DM, DM,
                                        0,0, 0,0, 0,0, 1, 1.f, 0, 1);
    }

    // 5. V^T per batch (values already rounded)
    {
        dim3 grid(DM/32, TT/32, NB);
        dim3 blk(32, 8);
        transpose_v_kernel<<<grid, blk>>>(v, vt);
    }

    // 6. scores = Q @ K^T / sqrt(HD), batched over (b,h)
    {
        dim3 grid(TT/BN, TT/BM, NB*NH);
        gemm_tf32_kernel<<<grid, 256, GEMM_SMEM_BYTES>>>(q, k, sc, nullptr, HD, DM, DM, TT,
                                        (long long)HD, LTTDM,
                                        (long long)HD, LTTDM,
                                        LTTTT, 16*LTTTT,
                                        NH, 0.08838834764831845f, 0, 0);
    }

    // 7. softmax rows (in place, rounded output)
    softmax_kernel<<<NB*NH*TT, 256>>>(sc);

    // 8. attn_out = P @ V (output rounded: feeds O-proj)
    {
        dim3 grid(HD/BN, TT/BM, NB*NH);
        gemm_tf32_kernel<<<grid, 256, GEMM_SMEM_BYTES>>>(sc, vt, attn, nullptr, TT, TT, TT, DM,
                                        LTTTT, 16*LTTTT,
                                        (long long)HD*TT, LTTDM,
                                        (long long)HD, LTTDM,
                                        NH, 1.f, 0, 1);
    }

    // 9. x1 = x + attn_out @ wo^T (full precision output)
    {
        dim3 grid(DM/BN, TOK/BM, 1);
        gemm_tf32_kernel<<<grid, 256, GEMM_SMEM_BYTES>>>(attn, rwo, x1, x, DM, DM, DM, DM,
                                        0,0, 0,0, 0,0, 1, 1.f, 1, 0);
    }

    // 10. h2 = round(LN2(x1))
    ln_kernel<<<TOK, 256>>>(x1, ln2w, ln2b, h2);

    // 11-12. gate / up (not mma inputs -> no rounding)
    {
        dim3 grid(DFF/BN, TOK/BM, 1);
        gemm_tf32_kernel<<<grid, 256, GEMM_SMEM_BYTES>>>(h2, rwg, gate, nullptr, DM, DM, DM, DFF,
                                        0,0, 0,0, 0,0, 1, 1.f, 0, 0);
        gemm_tf32_kernel<<<grid, 256, GEMM_SMEM_BYTES>>>(h2, rwu, up, nullptr, DM, DM, DM, DFF,
                                        0,0, 0,0, 0,0, 1, 1.f, 0, 0);
    }

    // 13. ff = round(silu(gate) * up)
    swiglu_kernel<<<(unsigned)((size_t)TOK*DFF/256), 256>>>(gate, up, ff);

    // 14. out = x1 + ff @ wd^T (full precision output)
    {
        dim3 grid(DM/BN, TOK/BM, 1);
        gemm_tf32_kernel<<<grid, 256, GEMM_SMEM_BYTES>>>(ff, rwd, out, x1, DFF, DFF, DFF, DM,
                                        0,0, 0,0, 0,0, 1, 1.f, 1, 0);
    }
}

// round 9
// speedup vs baseline: 1.8168x; 1.5908x over previous
#include <cuda_runtime.h>
#include <cuda_fp16.h>
#include <stdint.h>

// ---------------- problem constants ----------------
#define NB   2
#define TT   2048
#define DM   2048
#define NH   16
#define HD   128
#define DFF  8192
#define TOK  (NB*TT)

// ---------------- scratch (device globals) ----------------
__device__ __half g_h1  [(size_t)TOK*DM];
__device__ __half g_q   [(size_t)TOK*DM];
__device__ __half g_k   [(size_t)TOK*DM];
__device__ __half g_v   [(size_t)TOK*DM];
__device__ __half g_vT  [(size_t)TOK*DM];
__device__ float  g_sc  [(size_t)NB*NH*TT*TT];   // fp32 scores
__device__ __half g_scp [(size_t)NB*NH*TT*TT];   // fp16 probs
__device__ __half g_attn[(size_t)TOK*DM];
__device__ float  g_x1  [(size_t)TOK*DM];
__device__ __half g_h2  [(size_t)TOK*DM];
__device__ float  g_gate[(size_t)TOK*DFF];
__device__ float  g_up  [(size_t)TOK*DFF];
__device__ __half g_ff  [(size_t)TOK*DFF];
__device__ __half g_wq[(size_t)DM*DM];
__device__ __half g_wk[(size_t)DM*DM];
__device__ __half g_wv[(size_t)DM*DM];
__device__ __half g_wo[(size_t)DM*DM];
__device__ __half g_wg[(size_t)DFF*DM];
__device__ __half g_wu[(size_t)DFF*DM];
__device__ __half g_wd[(size_t)DM*DFF];

// ---------------- helpers ----------------
__device__ __forceinline__ void cpasync16(void* dst, const void* src) {
    uint32_t s = (uint32_t)__cvta_generic_to_shared(dst);
    asm volatile("cp.async.cg.shared.global [%0], [%1], 16;\n" :: "r"(s), "l"(src));
}

// ---------------- fp16 tensor-core GEMM ----------------
// C[m,n] = scale * sum_k A[m,k]*B[n,k] (+Res[m,n] if epi)
// A: [M,K] half, B: [N,K] half (K-major). OUTH=1 -> C half, else C float.
// Batched via blockIdx.z like before.
#define BM  128
#define BN  128
#define BK  32
#define SROW 40                    // halves per smem row (32 + 8 pad)
#define ASTG (BM*SROW)             // halves per stage per matrix (5120)
#define NSTAGE 3
#define GEMM_SMEM_BYTES (2*NSTAGE*ASTG*2)   // 61,440 B

extern __shared__ __half s16[];

template<int OUTH>
__global__ __launch_bounds__(256, 2)
void gemm_f16(const __half* __restrict__ A, const __half* __restrict__ Bm,
              void* __restrict__ Cv, const float* __restrict__ Res,
              int K, int lda, int ldb, int ldc,
              long long zaLo, long long zaHi,
              long long zbLo, long long zbHi,
              long long zcLo, long long zcHi,
              int zdiv, float scale, int epi)
{
    long long zq = blockIdx.z / zdiv, zr = blockIdx.z % zdiv;
    A  += zq*zaHi + zr*zaLo;
    Bm += zq*zbHi + zr*zbLo;
    const long long coff = zq*zcHi + zr*zcLo;
    if (epi) Res += coff;

    const int m0 = blockIdx.y * BM;
    const int n0 = blockIdx.x * BN;

    const int tid  = threadIdx.x;
    const int lane = tid & 31;
    const int warp = tid >> 5;
    const int mb   = (warp & 3) * 32;   // warp tile 32(M) x 64(N)
    const int nb   = (warp >> 2) * 64;

    float acc[2][8][4];
#pragma unroll
    for (int i = 0; i < 2; i++)
#pragma unroll
        for (int j = 0; j < 8; j++)
#pragma unroll
            for (int l = 0; l < 4; l++) acc[i][j][l] = 0.f;

    const int nK = K / BK;

    auto load_stage = [&](int st, int kt) {
        const int k0 = kt * BK;
        __half* sa = s16 + st * ASTG;
        __half* sb = s16 + NSTAGE * ASTG + st * ASTG;
#pragma unroll
        for (int i = 0; i < 2; i++) {
            int idx = tid + i * 256;          // 0..511
            int row = idx >> 2;               // 0..127
            int c8  = (idx & 3) << 3;         // 0,8,16,24 halves
            cpasync16(&sa[row*SROW + c8], A + (size_t)(m0+row)*lda + k0 + c8);
        }
#pragma unroll
        for (int i = 0; i < 2; i++) {
            int idx = tid + i * 256;
            int row = idx >> 2;
            int c8  = (idx & 3) << 3;
            cpasync16(&sb[row*SROW + c8], Bm + (size_t)(n0+row)*ldb + k0 + c8);
        }
    };

    load_stage(0, 0);
    asm volatile("cp.async.commit_group;\n");
    load_stage(1, 1);
    asm volatile("cp.async.commit_group;\n");

    for (int kt = 0; kt < nK; kt++) {
        asm volatile("cp.async.wait_group 1;\n");
        __syncthreads();

        if (kt + 2 < nK) load_stage((kt + 2) % NSTAGE, kt + 2);
        asm volatile("cp.async.commit_group;\n");

        const __half* As = s16 + (kt % NSTAGE) * ASTG;
        const __half* Bs = s16 + NSTAGE * ASTG + (kt % NSTAGE) * ASTG;
#pragma unroll
        for (int kk = 0; kk < BK; kk += 16) {
            uint32_t af[2][4];
#pragma unroll
            for (int im = 0; im < 2; im++) {
                int r = mb + im*16 + (lane >> 2);
                const __half* pa = As + r*SROW + kk + ((lane & 3) << 1);
                af[im][0] = *(const uint32_t*)pa;
                af[im][1] = *(const uint32_t*)(pa + 8*SROW);
                af[im][2] = *(const uint32_t*)(pa + 8);
                af[im][3] = *(const uint32_t*)(pa + 8*SROW + 8);
            }
            uint32_t bf[8][2];
#pragma unroll
            for (int in = 0; in < 8; in++) {
                int n = nb + in*8 + (lane >> 2);
                const __half* pb = Bs + n*SROW + kk + ((lane & 3) << 1);
                bf[in][0] = *(const uint32_t*)pb;
                bf[in][1] = *(const uint32_t*)(pb + 8);
            }
#pragma unroll
            for (int im = 0; im < 2; im++)
#pragma unroll
                for (int in = 0; in < 8; in++) {
                    asm volatile(
                        "mma.sync.aligned.m16n8k16.row.col.f32.f16.f16.f32 "
                        "{%0,%1,%2,%3}, {%4,%5,%6,%7}, {%8,%9}, {%0,%1,%2,%3};\n"
                        : "+f"(acc[im][in][0]), "+f"(acc[im][in][1]),
                          "+f"(acc[im][in][2]), "+f"(acc[im][in][3])
                        : "r"(af[im][0]), "r"(af[im][1]),
                          "r"(af[im][2]), "r"(af[im][3]),
                          "r"(bf[in][0]), "r"(bf[in][1]));
                }
        }
        __syncthreads();
    }

    // epilogue
#pragma unroll
    for (int im = 0; im < 2; im++) {
#pragma unroll
        for (int in = 0; in < 8; in++) {
            int r = m0 + mb + im*16 + (lane >> 2);
            int c = n0 + nb + in*8 + ((lane & 3) << 1);
            float v0 = acc[im][in][0] * scale;
            float v1 = acc[im][in][1] * scale;
            float v2 = acc[im][in][2] * scale;
            float v3 = acc[im][in][3] * scale;
            if (OUTH) {
                __half* C = (__half*)Cv + coff;
                *(__half2*)&C[(size_t)(r  )*ldc + c] = __floats2half2_rn(v0, v1);
                *(__half2*)&C[(size_t)(r+8)*ldc + c] = __floats2half2_rn(v2, v3);
            } else {
                float* C = (float*)Cv + coff;
                float2 t0 = {v0, v1}, t1 = {v2, v3};
                if (epi) {
                    float2 r0 = *(const float2*)&Res[(size_t)(r  )*ldc + c];
                    float2 r1 = *(const float2*)&Res[(size_t)(r+8)*ldc + c];
                    t0.x += r0.x; t0.y += r0.y;
                    t1.x += r1.x; t1.y += r1.y;
                }
                *(float2*)&C[(size_t)(r  )*ldc + c] = t0;
                *(float2*)&C[(size_t)(r+8)*ldc + c] = t1;
            }
        }
    }
}

// ---------------- weight conversion f32 -> f16 ----------------
__global__ __launch_bounds__(256)
void cvt_kernel(const float* __restrict__ in, __half* __restrict__ out, int n4)
{
    int i = blockIdx.x * 256 + threadIdx.x;
    if (i < n4) {
        float4 v = ((const float4*)in)[i];
        ((__half2*)out)[2*i    ] = __floats2half2_rn(v.x, v.y);
        ((__half2*)out)[2*i + 1] = __floats2half2_rn(v.z, v.w);
    }
}

// ---------------- LayerNorm (half output) ----------------
__global__ __launch_bounds__(256)
void ln_kernel(const float* __restrict__ x, const float* __restrict__ w,
               const float* __restrict__ b, __half* __restrict__ y)
{
    const int row = blockIdx.x;
    const float* xr = x + (size_t)row * DM;
    __half*      yr = y + (size_t)row * DM;

    float s = 0.f, sq = 0.f;
#pragma unroll
    for (int i = 0; i < DM/256; i++) {
        float v = xr[threadIdx.x + i*256];
        s += v; sq += v*v;
    }
#pragma unroll
    for (int o = 16; o; o >>= 1) {
        s  += __shfl_xor_sync(0xffffffffu, s,  o);
        sq += __shfl_xor_sync(0xffffffffu, sq, o);
    }
    __shared__ float sh[64];
    const int warp = threadIdx.x >> 5, lane = threadIdx.x & 31;
    if (lane == 0) { sh[warp] = s; sh[warp + 32] = sq; }
    __syncthreads();
    if (warp == 0) {
        s  = (lane < 8) ? sh[lane]      : 0.f;
        sq = (lane < 8) ? sh[lane + 32] : 0.f;
#pragma unroll
        for (int o = 4; o; o >>= 1) {
            s  += __shfl_xor_sync(0xffffffffu, s,  o);
            sq += __shfl_xor_sync(0xffffffffu, sq, o);
        }
        if (lane == 0) { sh[0] = s; sh[1] = sq; }
    }
    __syncthreads();
    const float mean = sh[0] * (1.f/DM);
    const float var  = sh[1] * (1.f/DM) - mean*mean;
    const float inv  = rsqrtf(var + 1e-5f);
#pragma unroll
    for (int i = 0; i < DM/256; i++) {
        int c = threadIdx.x + i*256;
        yr[c] = __float2half_rn((xr[c] - mean) * inv * w[c] + b[c]);
    }
}

// ---------------- softmax: fp32 scores -> fp16 probs ----------------
__global__ __launch_bounds__(256)
void softmax_kernel(const float* __restrict__ s, __half* __restrict__ p)
{
    const float* r = s + (size_t)blockIdx.x * TT;
    __half*      o = p + (size_t)blockIdx.x * TT;
    float v[TT/256];
    float mx = -1e30f;
#pragma unroll
    for (int i = 0; i < TT/256; i++) {
        v[i] = r[threadIdx.x + i*256];
        mx = fmaxf(mx, v[i]);
    }
#pragma unroll
    for (int ofs = 16; ofs; ofs >>= 1) mx = fmaxf(mx, __shfl_xor_sync(0xffffffffu, mx, ofs));
    __shared__ float sh[32];
    const int warp = threadIdx.x >> 5, lane = threadIdx.x & 31;
    if (lane == 0) sh[warp] = mx;
    __syncthreads();
    if (warp == 0) {
        mx = (lane < 8) ? sh[lane] : -1e30f;
#pragma unroll
        for (int ofs = 4; ofs; ofs >>= 1) mx = fmaxf(mx, __shfl_xor_sync(0xffffffffu, mx, ofs));
        if (lane == 0) sh[0] = mx;
    }
    __syncthreads();
    mx = sh[0];

    float sum = 0.f;
#pragma unroll
    for (int i = 0; i < TT/256; i++) { v[i] = __expf(v[i] - mx); sum += v[i]; }
#pragma unroll
    for (int ofs = 16; ofs; ofs >>= 1) sum += __shfl_xor_sync(0xffffffffu, sum, ofs);
    if (lane == 0) sh[warp] = sum;
    __syncthreads();
    if (warp == 0) {
        sum = (lane < 8) ? sh[lane] : 0.f;
#pragma unroll
        for (int ofs = 4; ofs; ofs >>= 1) sum += __shfl_xor_sync(0xffffffffu, sum, ofs);
        if (lane == 0) sh[0] = sum;
    }
    __syncthreads();
    const float inv = 1.f / sh[0];
#pragma unroll
    for (int i = 0; i < TT/256; i++)
        o[threadIdx.x + i*256] = __float2half_rn(v[i] * inv);
}

// ---------------- V -> V^T per batch (half) ----------------
__global__ void transpose_v_kernel(const __half* __restrict__ v, __half* __restrict__ vt)
{
    __shared__ __half tile[32][34];
    const int b  = blockIdx.z;
    const int x0 = blockIdx.x * 32;
    const int y0 = blockIdx.y * 32;
    const __half* vb = v  + (size_t)b * TT * DM;
    __half*      vtb = vt + (size_t)b * TT * DM;
    const int tx = threadIdx.x, ty = threadIdx.y;
#pragma unroll
    for (int i = 0; i < 32; i += 8)
        tile[ty + i][tx] = vb[(size_t)(y0 + ty + i) * DM + x0 + tx];
    __syncthreads();
#pragma unroll
    for (int i = 0; i < 32; i += 8)
        vtb[(size_t)(x0 + ty + i) * TT + y0 + tx] = tile[tx][ty + i];
}

// ---------------- SwiGLU: fp32 gate/up -> fp16 ff ----------------
__global__ __launch_bounds__(256)
void swiglu_kernel(const float* __restrict__ g, const float* __restrict__ u,
                   __half* __restrict__ o)
{
    size_t i = (size_t)blockIdx.x * 256 + threadIdx.x;
    float x = g[i];
    o[i] = __float2half_rn((x / (1.f + __expf(-x))) * u[i]);
}

// ---------------- launch ----------------
extern "C" void kernel_launch(void* const* d_in, const int* in_sizes, int n_in,
                              void* d_out, int out_size)
{
    const float* x     = (const float*)d_in[0];
    const float* wq    = (const float*)d_in[1];
    const float* wk    = (const float*)d_in[2];
    const float* wv    = (const float*)d_in[3];
    const float* wo    = (const float*)d_in[4];
    const float* wg    = (const float*)d_in[5];
    const float* wu    = (const float*)d_in[6];
    const float* wd    = (const float*)d_in[7];
    const float* ln1w  = (const float*)d_in[8];
    const float* ln1b  = (const float*)d_in[9];
    const float* ln2w  = (const float*)d_in[10];
    const float* ln2b  = (const float*)d_in[11];
    float* out = (float*)d_out;

    __half *h1, *q, *k, *v, *vt, *scp, *attn, *h2, *ff;
    float  *sc, *x1, *gate, *up;
    __half *rwq, *rwk, *rwv, *rwo, *rwg, *rwu, *rwd;
    cudaGetSymbolAddress((void**)&h1,   g_h1);
    cudaGetSymbolAddress((void**)&q,    g_q);
    cudaGetSymbolAddress((void**)&k,    g_k);
    cudaGetSymbolAddress((void**)&v,    g_v);
    cudaGetSymbolAddress((void**)&vt,   g_vT);
    cudaGetSymbolAddress((void**)&sc,   g_sc);
    cudaGetSymbolAddress((void**)&scp,  g_scp);
    cudaGetSymbolAddress((void**)&attn, g_attn);
    cudaGetSymbolAddress((void**)&x1,   g_x1);
    cudaGetSymbolAddress((void**)&h2,   g_h2);
    cudaGetSymbolAddress((void**)&gate, g_gate);
    cudaGetSymbolAddress((void**)&up,   g_up);
    cudaGetSymbolAddress((void**)&ff,   g_ff);
    cudaGetSymbolAddress((void**)&rwq,  g_wq);
    cudaGetSymbolAddress((void**)&rwk,  g_wk);
    cudaGetSymbolAddress((void**)&rwv,  g_wv);
    cudaGetSymbolAddress((void**)&rwo,  g_wo);
    cudaGetSymbolAddress((void**)&rwg,  g_wg);
    cudaGetSymbolAddress((void**)&rwu,  g_wu);
    cudaGetSymbolAddress((void**)&rwd,  g_wd);

    cudaFuncSetAttribute(gemm_f16<0>, cudaFuncAttributeMaxDynamicSharedMemorySize, GEMM_SMEM_BYTES);
    cudaFuncSetAttribute(gemm_f16<1>, cudaFuncAttributeMaxDynamicSharedMemorySize, GEMM_SMEM_BYTES);

    const long long LTTDM = (long long)TT * DM;
    const long long LTTTT = (long long)TT * TT;

    // 0. convert weights to fp16
    {
        int n4s = DM*DM/4, n4l = DFF*DM/4;
        cvt_kernel<<<(n4s+255)/256, 256>>>(wq, rwq, n4s);
        cvt_kernel<<<(n4s+255)/256, 256>>>(wk, rwk, n4s);
        cvt_kernel<<<(n4s+255)/256, 256>>>(wv, rwv, n4s);
        cvt_kernel<<<(n4s+255)/256, 256>>>(wo, rwo, n4s);
        cvt_kernel<<<(n4l+255)/256, 256>>>(wg, rwg, n4l);
        cvt_kernel<<<(n4l+255)/256, 256>>>(wu, rwu, n4l);
        cvt_kernel<<<(n4l+255)/256, 256>>>(wd, rwd, n4l);
    }

    // 1. h1 = half(LN1(x))
    ln_kernel<<<TOK, 256>>>(x, ln1w, ln1b, h1);

    // 2-4. Q, K, V projections (half outputs)
    {
        dim3 grid(DM/BN, TOK/BM, 1);
        gemm_f16<1><<<grid, 256, GEMM_SMEM_BYTES>>>(h1, rwq, q, nullptr, DM, DM, DM, DM,
                                        0,0, 0,0, 0,0, 1, 1.f, 0);
        gemm_f16<1><<<grid, 256, GEMM_SMEM_BYTES>>>(h1, rwk, k, nullptr, DM, DM, DM, DM,
                                        0,0, 0,0, 0,0, 1, 1.f, 0);
        gemm_f16<1><<<grid, 256, GEMM_SMEM_BYTES>>>(h1, rwv, v, nullptr, DM, DM, DM, DM,
                                        0,0, 0,0, 0,0, 1, 1.f, 0);
    }

    // 5. V^T per batch
    {
        dim3 grid(DM/32, TT/32, NB);
        dim3 blk(32, 8);
        transpose_v_kernel<<<grid, blk>>>(v, vt);
    }

    // 6. scores = Q @ K^T / sqrt(HD)  (fp32 out), z = b*16+h
    {
        dim3 grid(TT/BN, TT/BM, NB*NH);
        gemm_f16<0><<<grid, 256, GEMM_SMEM_BYTES>>>(q, k, sc, nullptr, HD, DM, DM, TT,
                                        (long long)HD, LTTDM,
                                        (long long)HD, LTTDM,
                                        LTTTT, 16*LTTTT,
                                        NH, 0.08838834764831845f, 0);
    }

    // 7. softmax -> half probs
    softmax_kernel<<<NB*NH*TT, 256>>>(sc, scp);

    // 8. attn = P @ V (half out)
    {
        dim3 grid(HD/BN, TT/BM, NB*NH);
        gemm_f16<1><<<grid, 256, GEMM_SMEM_BYTES>>>(scp, vt, attn, nullptr, TT, TT, TT, DM,
                                        LTTTT, 16*LTTTT,
                                        (long long)HD*TT, LTTDM,
                                        (long long)HD, LTTDM,
                                        NH, 1.f, 0);
    }

    // 9. x1 = x + attn @ wo^T (fp32 out + residual)
    {
        dim3 grid(DM/BN, TOK/BM, 1);
        gemm_f16<0><<<grid, 256, GEMM_SMEM_BYTES>>>(attn, rwo, x1, x, DM, DM, DM, DM,
                                        0,0, 0,0, 0,0, 1, 1.f, 1);
    }

    // 10. h2 = half(LN2(x1))
    ln_kernel<<<TOK, 256>>>(x1, ln2w, ln2b, h2);

    // 11-12. gate / up (fp32 outs)
    {
        dim3 grid(DFF/BN, TOK/BM, 1);
        gemm_f16<0><<<grid, 256, GEMM_SMEM_BYTES>>>(h2, rwg, gate, nullptr, DM, DM, DM, DFF,
                                        0,0, 0,0, 0,0, 1, 1.f, 0);
        gemm_f16<0><<<grid, 256, GEMM_SMEM_BYTES>>>(h2, rwu, up, nullptr, DM, DM, DM, DFF,
                                        0,0, 0,0, 0,0, 1, 1.f, 0);
    }

    // 13. ff = half(silu(gate) * up)
    swiglu_kernel<<<(unsigned)((size_t)TOK*DFF/256), 256>>>(gate, up, ff);

    // 14. out = x1 + ff @ wd^T (fp32 out + residual)
    {
        dim3 grid(DM/BN, TOK/BM, 1);
        gemm_f16<0><<<grid, 256, GEMM_SMEM_BYTES>>>(ff, rwd, out, x1, DFF, DFF, DFF, DM,
                                        0,0, 0,0, 0,0, 1, 1.f, 1);
    }
}

// round 11
// speedup vs baseline: 1.9075x; 1.0499x over previous
#include <cuda_runtime.h>
#include <cuda_fp16.h>
#include <stdint.h>

// ---------------- problem constants ----------------
#define NB   2
#define TT   2048
#define DM   2048
#define NH   16
#define HD   128
#define DFF  8192
#define TOK  (NB*TT)

// ---------------- scratch (device globals) ----------------
__device__ __half g_h1  [(size_t)TOK*DM];
__device__ __half g_q   [(size_t)TOK*DM];
__device__ __half g_k   [(size_t)TOK*DM];
__device__ __half g_v   [(size_t)TOK*DM];
__device__ __half g_vT  [(size_t)TOK*DM];
__device__ float  g_sc  [(size_t)NB*NH*TT*TT];   // fp32 scores
__device__ __half g_scp [(size_t)NB*NH*TT*TT];   // fp16 probs
__device__ __half g_attn[(size_t)TOK*DM];
__device__ float  g_x1  [(size_t)TOK*DM];
__device__ __half g_h2  [(size_t)TOK*DM];
__device__ float  g_gate[(size_t)TOK*DFF];
__device__ float  g_up  [(size_t)TOK*DFF];
__device__ __half g_ff  [(size_t)TOK*DFF];
__device__ __half g_wq[(size_t)DM*DM];
__device__ __half g_wk[(size_t)DM*DM];
__device__ __half g_wv[(size_t)DM*DM];
__device__ __half g_wo[(size_t)DM*DM];
__device__ __half g_wg[(size_t)DFF*DM];
__device__ __half g_wu[(size_t)DFF*DM];
__device__ __half g_wd[(size_t)DM*DFF];

// ---------------- helpers ----------------
__device__ __forceinline__ void cpasync16(void* dst, const void* src) {
    uint32_t s = (uint32_t)__cvta_generic_to_shared(dst);
    asm volatile("cp.async.cg.shared.global [%0], [%1], 16;\n" :: "r"(s), "l"(src));
}

__device__ __forceinline__ void ldsm_x4(uint32_t& r0, uint32_t& r1,
                                        uint32_t& r2, uint32_t& r3, uint32_t addr) {
    asm volatile("ldmatrix.sync.aligned.m8n8.x4.shared.b16 {%0,%1,%2,%3}, [%4];"
                 : "=r"(r0), "=r"(r1), "=r"(r2), "=r"(r3) : "r"(addr));
}

// ---------------- fp16 tensor-core GEMM ----------------
// C[m,n] = scale * sum_k A[m,k]*B[n,k] (+Res[m,n] if epi)
// A: [M,K] half, B: [N,K] half (K-major). OUTH=1 -> C half, else C float.
#define BM  128
#define BN  128
#define BK  32
#define SROW 40                    // halves per smem row (32 + 8 pad)
#define ASTG (BM*SROW)             // halves per stage per matrix (5120)
#define NSTAGE 3
#define GEMM_SMEM_BYTES (2*NSTAGE*ASTG*2)   // 61,440 B

extern __shared__ __half s16[];

template<int OUTH>
__global__ __launch_bounds__(256, 2)
void gemm_f16(const __half* __restrict__ A, const __half* __restrict__ Bm,
              void* __restrict__ Cv, const float* __restrict__ Res,
              int K, int lda, int ldb, int ldc,
              long long zaLo, long long zaHi,
              long long zbLo, long long zbHi,
              long long zcLo, long long zcHi,
              int zdiv, float scale, int epi)
{
    long long zq = blockIdx.z / zdiv, zr = blockIdx.z % zdiv;
    A  += zq*zaHi + zr*zaLo;
    Bm += zq*zbHi + zr*zbLo;
    const long long coff = zq*zcHi + zr*zcLo;
    if (epi) Res += coff;

    const int m0 = blockIdx.y * BM;
    const int n0 = blockIdx.x * BN;

    const int tid  = threadIdx.x;
    const int lane = tid & 31;
    const int warp = tid >> 5;
    const int mb   = (warp & 3) * 32;   // warp tile 32(M) x 64(N)
    const int nb   = (warp >> 2) * 64;

    float acc[2][8][4];
#pragma unroll
    for (int i = 0; i < 2; i++)
#pragma unroll
        for (int j = 0; j < 8; j++)
#pragma unroll
            for (int l = 0; l < 4; l++) acc[i][j][l] = 0.f;

    const int nK = K / BK;

    // ldmatrix lane-address offsets (bytes) within a stage
    const uint32_t s16u = (uint32_t)__cvta_generic_to_shared(s16);
    const int lrow  = lane & 15;           // row within 16-row group
    const int lchnk = (lane >> 4) * 8;     // 0 or 8 halves (k chunk)
    const uint32_t aoff0 = (uint32_t)(((mb + lrow) * SROW + lchnk) * 2);
    const uint32_t aoff1 = aoff0 + 16 * SROW * 2;
    uint32_t boff[4];
#pragma unroll
    for (int p = 0; p < 4; p++)
        boff[p] = (uint32_t)(((nb + p*16 + lrow) * SROW + lchnk) * 2) + NSTAGE * ASTG * 2;

    auto load_stage = [&](int st, int kt) {
        const int k0 = kt * BK;
        __half* sa = s16 + st * ASTG;
        __half* sb = s16 + NSTAGE * ASTG + st * ASTG;
#pragma unroll
        for (int i = 0; i < 2; i++) {
            int idx = tid + i * 256;          // 0..511
            int row = idx >> 2;               // 0..127
            int c8  = (idx & 3) << 3;         // 0,8,16,24 halves
            cpasync16(&sa[row*SROW + c8], A + (size_t)(m0+row)*lda + k0 + c8);
        }
#pragma unroll
        for (int i = 0; i < 2; i++) {
            int idx = tid + i * 256;
            int row = idx >> 2;
            int c8  = (idx & 3) << 3;
            cpasync16(&sb[row*SROW + c8], Bm + (size_t)(n0+row)*ldb + k0 + c8);
        }
    };

    load_stage(0, 0);
    asm volatile("cp.async.commit_group;\n");
    load_stage(1, 1);
    asm volatile("cp.async.commit_group;\n");

    for (int kt = 0; kt < nK; kt++) {
        asm volatile("cp.async.wait_group 1;\n");
        __syncthreads();

        if (kt + 2 < nK) load_stage((kt + 2) % NSTAGE, kt + 2);
        asm volatile("cp.async.commit_group;\n");

        const uint32_t stg = s16u + (uint32_t)((kt % NSTAGE) * ASTG * 2);
#pragma unroll
        for (int kk = 0; kk < BK; kk += 16) {
            const uint32_t kb = stg + kk * 2;
            uint32_t af[2][4];
            ldsm_x4(af[0][0], af[0][1], af[0][2], af[0][3], kb + aoff0);
            ldsm_x4(af[1][0], af[1][1], af[1][2], af[1][3], kb + aoff1);
            uint32_t bf[8][2];
#pragma unroll
            for (int p = 0; p < 4; p++) {
                // x4 over two n-tiles: m0=n(2p) k0-7, m1=n(2p+1) k0-7,
                //                      m2=n(2p) k8-15, m3=n(2p+1) k8-15
                ldsm_x4(bf[2*p][0], bf[2*p+1][0], bf[2*p][1], bf[2*p+1][1], kb + boff[p]);
            }
#pragma unroll
            for (int im = 0; im < 2; im++)
#pragma unroll
                for (int in = 0; in < 8; in++) {
                    asm volatile(
                        "mma.sync.aligned.m16n8k16.row.col.f32.f16.f16.f32 "
                        "{%0,%1,%2,%3}, {%4,%5,%6,%7}, {%8,%9}, {%0,%1,%2,%3};\n"
                        : "+f"(acc[im][in][0]), "+f"(acc[im][in][1]),
                          "+f"(acc[im][in][2]), "+f"(acc[im][in][3])
                        : "r"(af[im][0]), "r"(af[im][1]),
                          "r"(af[im][2]), "r"(af[im][3]),
                          "r"(bf[in][0]), "r"(bf[in][1]));
                }
        }
        __syncthreads();
    }

    // epilogue
#pragma unroll
    for (int im = 0; im < 2; im++) {
#pragma unroll
        for (int in = 0; in < 8; in++) {
            int r = m0 + mb + im*16 + (lane >> 2);
            int c = n0 + nb + in*8 + ((lane & 3) << 1);
            float v0 = acc[im][in][0] * scale;
            float v1 = acc[im][in][1] * scale;
            float v2 = acc[im][in][2] * scale;
            float v3 = acc[im][in][3] * scale;
            if (OUTH) {
                __half* C = (__half*)Cv + coff;
                *(__half2*)&C[(size_t)(r  )*ldc + c] = __floats2half2_rn(v0, v1);
                *(__half2*)&C[(size_t)(r+8)*ldc + c] = __floats2half2_rn(v2, v3);
            } else {
                float* C = (float*)Cv + coff;
                float2 t0 = {v0, v1}, t1 = {v2, v3};
                if (epi) {
                    float2 r0 = *(const float2*)&Res[(size_t)(r  )*ldc + c];
                    float2 r1 = *(const float2*)&Res[(size_t)(r+8)*ldc + c];
                    t0.x += r0.x; t0.y += r0.y;
                    t1.x += r1.x; t1.y += r1.y;
                }
                *(float2*)&C[(size_t)(r  )*ldc + c] = t0;
                *(float2*)&C[(size_t)(r+8)*ldc + c] = t1;
            }
        }
    }
}

// ---------------- merged weight conversion f32 -> f16 ----------------
// 4 small (DM*DM) + 3 large (DFF*DM) weights in one grid-stride launch.
#define S4 (DM*DM/4)
#define L4 (DFF*DM/4)
__global__ __launch_bounds__(256)
void cvt_all_kernel(const float* __restrict__ wq, const float* __restrict__ wk,
                    const float* __restrict__ wv, const float* __restrict__ wo,
                    const float* __restrict__ wg, const float* __restrict__ wu,
                    const float* __restrict__ wd,
                    __half* __restrict__ oq, __half* __restrict__ ok,
                    __half* __restrict__ ov, __half* __restrict__ oo,
                    __half* __restrict__ og, __half* __restrict__ ou,
                    __half* __restrict__ od)
{
    int i = blockIdx.x * 256 + threadIdx.x;   // 0 .. 4*S4 + 3*L4 - 1
    const float* src; __half* dst; int off;
    if (i < 4*S4) {
        int w = i / S4; off = i - w*S4;
        src = (w == 0) ? wq : (w == 1) ? wk : (w == 2) ? wv : wo;
        dst = (w == 0) ? oq : (w == 1) ? ok : (w == 2) ? ov : oo;
    } else {
        int j = i - 4*S4;
        int w = j / L4; off = j - w*L4;
        src = (w == 0) ? wg : (w == 1) ? wu : wd;
        dst = (w == 0) ? og : (w == 1) ? ou : od;
    }
    float4 v = ((const float4*)src)[off];
    ((__half2*)dst)[2*off    ] = __floats2half2_rn(v.x, v.y);
    ((__half2*)dst)[2*off + 1] = __floats2half2_rn(v.z, v.w);
}

// ---------------- LayerNorm (half output) ----------------
__global__ __launch_bounds__(256)
void ln_kernel(const float* __restrict__ x, const float* __restrict__ w,
               const float* __restrict__ b, __half* __restrict__ y)
{
    const int row = blockIdx.x;
    const float* xr = x + (size_t)row * DM;
    __half*      yr = y + (size_t)row * DM;

    float s = 0.f, sq = 0.f;
#pragma unroll
    for (int i = 0; i < DM/256; i++) {
        float v = xr[threadIdx.x + i*256];
        s += v; sq += v*v;
    }
#pragma unroll
    for (int o = 16; o; o >>= 1) {
        s  += __shfl_xor_sync(0xffffffffu, s,  o);
        sq += __shfl_xor_sync(0xffffffffu, sq, o);
    }
    __shared__ float sh[64];
    const int warp = threadIdx.x >> 5, lane = threadIdx.x & 31;
    if (lane == 0) { sh[warp] = s; sh[warp + 32] = sq; }
    __syncthreads();
    if (warp == 0) {
        s  = (lane < 8) ? sh[lane]      : 0.f;
        sq = (lane < 8) ? sh[lane + 32] : 0.f;
#pragma unroll
        for (int o = 4; o; o >>= 1) {
            s  += __shfl_xor_sync(0xffffffffu, s,  o);
            sq += __shfl_xor_sync(0xffffffffu, sq, o);
        }
        if (lane == 0) { sh[0] = s; sh[1] = sq; }
    }
    __syncthreads();
    const float mean = sh[0] * (1.f/DM);
    const float var  = sh[1] * (1.f/DM) - mean*mean;
    const float inv  = rsqrtf(var + 1e-5f);
#pragma unroll
    for (int i = 0; i < DM/256; i++) {
        int c = threadIdx.x + i*256;
        yr[c] = __float2half_rn((xr[c] - mean) * inv * w[c] + b[c]);
    }
}

// ---------------- softmax: fp32 scores -> fp16 probs ----------------
__global__ __launch_bounds__(256)
void softmax_kernel(const float* __restrict__ s, __half* __restrict__ p)
{
    const float* r = s + (size_t)blockIdx.x * TT;
    __half*      o = p + (size_t)blockIdx.x * TT;
    float v[TT/256];
    float mx = -1e30f;
#pragma unroll
    for (int i = 0; i < TT/256; i++) {
        v[i] = r[threadIdx.x + i*256];
        mx = fmaxf(mx, v[i]);
    }
#pragma unroll
    for (int ofs = 16; ofs; ofs >>= 1) mx = fmaxf(mx, __shfl_xor_sync(0xffffffffu, mx, ofs));
    __shared__ float sh[32];
    const int warp = threadIdx.x >> 5, lane = threadIdx.x & 31;
    if (lane == 0) sh[warp] = mx;
    __syncthreads();
    if (warp == 0) {
        mx = (lane < 8) ? sh[lane] : -1e30f;
#pragma unroll
        for (int ofs = 4; ofs; ofs >>= 1) mx = fmaxf(mx, __shfl_xor_sync(0xffffffffu, mx, ofs));
        if (lane == 0) sh[0] = mx;
    }
    __syncthreads();
    mx = sh[0];

    float sum = 0.f;
#pragma unroll
    for (int i = 0; i < TT/256; i++) { v[i] = __expf(v[i] - mx); sum += v[i]; }
#pragma unroll
    for (int ofs = 16; ofs; ofs >>= 1) sum += __shfl_xor_sync(0xffffffffu, sum, ofs);
    if (lane == 0) sh[warp] = sum;
    __syncthreads();
    if (warp == 0) {
        sum = (lane < 8) ? sh[lane] : 0.f;
#pragma unroll
        for (int ofs = 4; ofs; ofs >>= 1) sum += __shfl_xor_sync(0xffffffffu, sum, ofs);
        if (lane == 0) sh[0] = sum;
    }
    __syncthreads();
    const float inv = 1.f / sh[0];
#pragma unroll
    for (int i = 0; i < TT/256; i++)
        o[threadIdx.x + i*256] = __float2half_rn(v[i] * inv);
}

// ---------------- V -> V^T per batch (half) ----------------
__global__ void transpose_v_kernel(const __half* __restrict__ v, __half* __restrict__ vt)
{
    __shared__ __half tile[32][34];
    const int b  = blockIdx.z;
    const int x0 = blockIdx.x * 32;
    const int y0 = blockIdx.y * 32;
    const __half* vb = v  + (size_t)b * TT * DM;
    __half*      vtb = vt + (size_t)b * TT * DM;
    const int tx = threadIdx.x, ty = threadIdx.y;
#pragma unroll
    for (int i = 0; i < 32; i += 8)
        tile[ty + i][tx] = vb[(size_t)(y0 + ty + i) * DM + x0 + tx];
    __syncthreads();
#pragma unroll
    for (int i = 0; i < 32; i += 8)
        vtb[(size_t)(x0 + ty + i) * TT + y0 + tx] = tile[tx][ty + i];
}

// ---------------- SwiGLU: fp32 gate/up -> fp16 ff ----------------
__global__ __launch_bounds__(256)
void swiglu_kernel(const float* __restrict__ g, const float* __restrict__ u,
                   __half* __restrict__ o)
{
    size_t i = (size_t)blockIdx.x * 256 + threadIdx.x;
    float x = g[i];
    o[i] = __float2half_rn((x / (1.f + __expf(-x))) * u[i]);
}

// ---------------- launch ----------------
extern "C" void kernel_launch(void* const* d_in, const int* in_sizes, int n_in,
                              void* d_out, int out_size)
{
    const float* x     = (const float*)d_in[0];
    const float* wq    = (const float*)d_in[1];
    const float* wk    = (const float*)d_in[2];
    const float* wv    = (const float*)d_in[3];
    const float* wo    = (const float*)d_in[4];
    const float* wg    = (const float*)d_in[5];
    const float* wu    = (const float*)d_in[6];
    const float* wd    = (const float*)d_in[7];
    const float* ln1w  = (const float*)d_in[8];
    const float* ln1b  = (const float*)d_in[9];
    const float* ln2w  = (const float*)d_in[10];
    const float* ln2b  = (const float*)d_in[11];
    float* out = (float*)d_out;

    __half *h1, *q, *k, *v, *vt, *scp, *attn, *h2, *ff;
    float  *sc, *x1, *gate, *up;
    __half *rwq, *rwk, *rwv, *rwo, *rwg, *rwu, *rwd;
    cudaGetSymbolAddress((void**)&h1,   g_h1);
    cudaGetSymbolAddress((void**)&q,    g_q);
    cudaGetSymbolAddress((void**)&k,    g_k);
    cudaGetSymbolAddress((void**)&v,    g_v);
    cudaGetSymbolAddress((void**)&vt,   g_vT);
    cudaGetSymbolAddress((void**)&sc,   g_sc);
    cudaGetSymbolAddress((void**)&scp,  g_scp);
    cudaGetSymbolAddress((void**)&attn, g_attn);
    cudaGetSymbolAddress((void**)&x1,   g_x1);
    cudaGetSymbolAddress((void**)&h2,   g_h2);
    cudaGetSymbolAddress((void**)&gate, g_gate);
    cudaGetSymbolAddress((void**)&up,   g_up);
    cudaGetSymbolAddress((void**)&ff,   g_ff);
    cudaGetSymbolAddress((void**)&rwq,  g_wq);
    cudaGetSymbolAddress((void**)&rwk,  g_wk);
    cudaGetSymbolAddress((void**)&rwv,  g_wv);
    cudaGetSymbolAddress((void**)&rwo,  g_wo);
    cudaGetSymbolAddress((void**)&rwg,  g_wg);
    cudaGetSymbolAddress((void**)&rwu,  g_wu);
    cudaGetSymbolAddress((void**)&rwd,  g_wd);

    cudaFuncSetAttribute(gemm_f16<0>, cudaFuncAttributeMaxDynamicSharedMemorySize, GEMM_SMEM_BYTES);
    cudaFuncSetAttribute(gemm_f16<1>, cudaFuncAttributeMaxDynamicSharedMemorySize, GEMM_SMEM_BYTES);

    const long long LTTDM = (long long)TT * DM;
    const long long LTTTT = (long long)TT * TT;

    // 0. convert all weights to fp16 (single launch)
    {
        int total = 4*S4 + 3*L4;   // 16,777,216
        cvt_all_kernel<<<total/256, 256>>>(wq, wk, wv, wo, wg, wu, wd,
                                           rwq, rwk, rwv, rwo, rwg, rwu, rwd);
    }

    // 1. h1 = half(LN1(x))
    ln_kernel<<<TOK, 256>>>(x, ln1w, ln1b, h1);

    // 2-4. Q, K, V projections (half outputs)
    {
        dim3 grid(DM/BN, TOK/BM, 1);
        gemm_f16<1><<<grid, 256, GEMM_SMEM_BYTES>>>(h1, rwq, q, nullptr, DM, DM, DM, DM,
                                        0,0, 0,0, 0,0, 1, 1.f, 0);
        gemm_f16<1><<<grid, 256, GEMM_SMEM_BYTES>>>(h1, rwk, k, nullptr, DM, DM, DM, DM,
                                        0,0, 0,0, 0,0, 1, 1.f, 0);
        gemm_f16<1><<<grid, 256, GEMM_SMEM_BYTES>>>(h1, rwv, v, nullptr, DM, DM, DM, DM,
                                        0,0, 0,0, 0,0, 1, 1.f, 0);
    }

    // 5. V^T per batch
    {
        dim3 grid(DM/32, TT/32, NB);
        dim3 blk(32, 8);
        transpose_v_kernel<<<grid, blk>>>(v, vt);
    }

    // 6. scores = Q @ K^T / sqrt(HD)  (fp32 out), z = b*16+h
    {
        dim3 grid(TT/BN, TT/BM, NB*NH);
        gemm_f16<0><<<grid, 256, GEMM_SMEM_BYTES>>>(q, k, sc, nullptr, HD, DM, DM, TT,
                                        (long long)HD, LTTDM,
                                        (long long)HD, LTTDM,
                                        LTTTT, 16*LTTTT,
                                        NH, 0.08838834764831845f, 0);
    }

    // 7. softmax -> half probs
    softmax_kernel<<<NB*NH*TT, 256>>>(sc, scp);

    // 8. attn = P @ V (half out)
    {
        dim3 grid(HD/BN, TT/BM, NB*NH);
        gemm_f16<1><<<grid, 256, GEMM_SMEM_BYTES>>>(scp, vt, attn, nullptr, TT, TT, TT, DM,
                                        LTTTT, 16*LTTTT,
                                        (long long)HD*TT, LTTDM,
                                        (long long)HD, LTTDM,
                                        NH, 1.f, 0);
    }

    // 9. x1 = x + attn @ wo^T (fp32 out + residual)
    {
        dim3 grid(DM/BN, TOK/BM, 1);
        gemm_f16<0><<<grid, 256, GEMM_SMEM_BYTES>>>(attn, rwo, x1, x, DM, DM, DM, DM,
                                        0,0, 0,0, 0,0, 1, 1.f, 1);
    }

    // 10. h2 = half(LN2(x1))
    ln_kernel<<<TOK, 256>>>(x1, ln2w, ln2b, h2);

    // 11-12. gate / up (fp32 outs)
    {
        dim3 grid(DFF/BN, TOK/BM, 1);
        gemm_f16<0><<<grid, 256, GEMM_SMEM_BYTES>>>(h2, rwg, gate, nullptr, DM, DM, DM, DFF,
                                        0,0, 0,0, 0,0, 1, 1.f, 0);
        gemm_f16<0><<<grid, 256, GEMM_SMEM_BYTES>>>(h2, rwu, up, nullptr, DM, DM, DM, DFF,
                                        0,0, 0,0, 0,0, 1, 1.f, 0);
    }

    // 13. ff = half(silu(gate) * up)
    swiglu_kernel<<<(unsigned)((size_t)TOK*DFF/256), 256>>>(gate, up, ff);

    // 14. out = x1 + ff @ wd^T (fp32 out + residual)
    {
        dim3 grid(DM/BN, TOK/BM, 1);
        gemm_f16<0><<<grid, 256, GEMM_SMEM_BYTES>>>(ff, rwd, out, x1, DFF, DFF, DFF, DM,
                                        0,0, 0,0, 0,0, 1, 1.f, 1);
    }
}

// round 13
// speedup vs baseline: 1.9377x; 1.0159x over previous
#include <cuda_runtime.h>
#include <cuda_fp16.h>
#include <stdint.h>

// ---------------- problem constants ----------------
#define NB   2
#define TT   2048
#define DM   2048
#define NH   16
#define HD   128
#define DFF  8192
#define TOK  (NB*TT)

// ---------------- scratch (device globals) ----------------
__device__ __half g_h1  [(size_t)TOK*DM];
__device__ __half g_q   [(size_t)TOK*DM];
__device__ __half g_k   [(size_t)TOK*DM];
__device__ __half g_v   [(size_t)TOK*DM];
__device__ __half g_vT  [(size_t)TOK*DM];
__device__ float  g_sc  [(size_t)NB*NH*TT*TT];   // fp32 scores
__device__ __half g_scp [(size_t)NB*NH*TT*TT];   // fp16 probs
__device__ __half g_attn[(size_t)TOK*DM];
__device__ float  g_x1  [(size_t)TOK*DM];
__device__ __half g_h2  [(size_t)TOK*DM];
__device__ float  g_gate[(size_t)TOK*DFF];
__device__ __half g_ff  [(size_t)TOK*DFF];
__device__ __half g_wq[(size_t)DM*DM];
__device__ __half g_wk[(size_t)DM*DM];
__device__ __half g_wv[(size_t)DM*DM];
__device__ __half g_wo[(size_t)DM*DM];
__device__ __half g_wg[(size_t)DFF*DM];
__device__ __half g_wu[(size_t)DFF*DM];
__device__ __half g_wd[(size_t)DM*DFF];

// ---------------- helpers ----------------
__device__ __forceinline__ void cpasync16(void* dst, const void* src) {
    uint32_t s = (uint32_t)__cvta_generic_to_shared(dst);
    asm volatile("cp.async.cg.shared.global [%0], [%1], 16;\n" :: "r"(s), "l"(src));
}

__device__ __forceinline__ void ldsm_x4(uint32_t& r0, uint32_t& r1,
                                        uint32_t& r2, uint32_t& r3, uint32_t addr) {
    asm volatile("ldmatrix.sync.aligned.m8n8.x4.shared.b16 {%0,%1,%2,%3}, [%4];"
                 : "=r"(r0), "=r"(r1), "=r"(r2), "=r"(r3) : "r"(addr));
}

// ---------------- fp16 tensor-core GEMM ----------------
// C[m,n] = scale * sum_k A[m,k]*B[n,k]
// epi=1 (OUTH=0): += Res.   epi=2 (OUTH=1): C = silu(Res) * acc  (SwiGLU fuse)
#define BM  128
#define BN  128
#define BK  32
#define SROW 40                    // halves per smem row (32 + 8 pad)
#define ASTG (BM*SROW)             // halves per stage per matrix (5120)
#define NSTAGE 4
#define GEMM_SMEM_BYTES (2*NSTAGE*ASTG*2)   // 81,920 B

extern __shared__ __half s16[];

template<int OUTH>
__global__ __launch_bounds__(256, 2)
void gemm_f16(const __half* __restrict__ A, const __half* __restrict__ Bm,
              void* __restrict__ Cv, const float* __restrict__ Res,
              int K, int lda, int ldb, int ldc,
              long long zaLo, long long zaHi,
              long long zbLo, long long zbHi,
              long long zcLo, long long zcHi,
              int zdiv, float scale, int epi)
{
    long long zq = blockIdx.z / zdiv, zr = blockIdx.z % zdiv;
    A  += zq*zaHi + zr*zaLo;
    Bm += zq*zbHi + zr*zbLo;
    const long long coff = zq*zcHi + zr*zcLo;
    if (epi) Res += coff;

    const int m0 = blockIdx.y * BM;
    const int n0 = blockIdx.x * BN;

    const int tid  = threadIdx.x;
    const int lane = tid & 31;
    const int warp = tid >> 5;
    const int mb   = (warp & 3) * 32;   // warp tile 32(M) x 64(N)
    const int nb   = (warp >> 2) * 64;

    float acc[2][8][4];
#pragma unroll
    for (int i = 0; i < 2; i++)
#pragma unroll
        for (int j = 0; j < 8; j++)
#pragma unroll
            for (int l = 0; l < 4; l++) acc[i][j][l] = 0.f;

    const int nK = K / BK;   // >= 4 for all shapes here

    // ldmatrix lane-address offsets (bytes) within a stage
    const uint32_t s16u = (uint32_t)__cvta_generic_to_shared(s16);
    const int lrow  = lane & 15;           // row within 16-row group
    const int lchnk = (lane >> 4) * 8;     // 0 or 8 halves (k chunk)
    const uint32_t aoff0 = (uint32_t)(((mb + lrow) * SROW + lchnk) * 2);
    const uint32_t aoff1 = aoff0 + 16 * SROW * 2;
    uint32_t boff[4];
#pragma unroll
    for (int p = 0; p < 4; p++)
        boff[p] = (uint32_t)(((nb + p*16 + lrow) * SROW + lchnk) * 2) + NSTAGE * ASTG * 2;

    auto load_stage = [&](int st, int kt) {
        const int k0 = kt * BK;
        __half* sa = s16 + st * ASTG;
        __half* sb = s16 + NSTAGE * ASTG + st * ASTG;
#pragma unroll
        for (int i = 0; i < 2; i++) {
            int idx = tid + i * 256;          // 0..511
            int row = idx >> 2;               // 0..127
            int c8  = (idx & 3) << 3;         // 0,8,16,24 halves
            cpasync16(&sa[row*SROW + c8], A + (size_t)(m0+row)*lda + k0 + c8);
        }
#pragma unroll
        for (int i = 0; i < 2; i++) {
            int idx = tid + i * 256;
            int row = idx >> 2;
            int c8  = (idx & 3) << 3;
            cpasync16(&sb[row*SROW + c8], Bm + (size_t)(n0+row)*ldb + k0 + c8);
        }
    };

    auto compute = [&](int slot) {
        const uint32_t stg = s16u + (uint32_t)(slot * ASTG * 2);
#pragma unroll
        for (int kk = 0; kk < BK; kk += 16) {
            const uint32_t kb = stg + kk * 2;
            uint32_t af[2][4];
            ldsm_x4(af[0][0], af[0][1], af[0][2], af[0][3], kb + aoff0);
            ldsm_x4(af[1][0], af[1][1], af[1][2], af[1][3], kb + aoff1);
            uint32_t bf[8][2];
#pragma unroll
            for (int p = 0; p < 4; p++) {
                ldsm_x4(bf[2*p][0], bf[2*p+1][0], bf[2*p][1], bf[2*p+1][1], kb + boff[p]);
            }
#pragma unroll
            for (int im = 0; im < 2; im++)
#pragma unroll
                for (int in = 0; in < 8; in++) {
                    asm volatile(
                        "mma.sync.aligned.m16n8k16.row.col.f32.f16.f16.f32 "
                        "{%0,%1,%2,%3}, {%4,%5,%6,%7}, {%8,%9}, {%0,%1,%2,%3};\n"
                        : "+f"(acc[im][in][0]), "+f"(acc[im][in][1]),
                          "+f"(acc[im][in][2]), "+f"(acc[im][in][3])
                        : "r"(af[im][0]), "r"(af[im][1]),
                          "r"(af[im][2]), "r"(af[im][3]),
                          "r"(bf[in][0]), "r"(bf[in][1]));
                }
        }
    };

    // prologue: 3 stages in flight
    load_stage(0, 0);
    asm volatile("cp.async.commit_group;\n");
    load_stage(1, 1);
    asm volatile("cp.async.commit_group;\n");
    load_stage(2, 2);
    asm volatile("cp.async.commit_group;\n");

    for (int kt = 0; kt < nK; kt++) {
        // retire stage kt's copy group (per-thread), then publish via barrier
        if (kt + 2 < nK)      asm volatile("cp.async.wait_group 2;\n");
        else if (kt + 1 < nK) asm volatile("cp.async.wait_group 1;\n");
        else                  asm volatile("cp.async.wait_group 0;\n");
        __syncthreads();

        if (kt + 3 < nK) {
            load_stage((kt + 3) & 3, kt + 3);   // slot (kt-1)&3: reads done pre-barrier
            asm volatile("cp.async.commit_group;\n");
        }

        compute(kt & 3);
    }

    // epilogue
#pragma unroll
    for (int im = 0; im < 2; im++) {
#pragma unroll
        for (int in = 0; in < 8; in++) {
            int r = m0 + mb + im*16 + (lane >> 2);
            int c = n0 + nb + in*8 + ((lane & 3) << 1);
            float v0 = acc[im][in][0] * scale;
            float v1 = acc[im][in][1] * scale;
            float v2 = acc[im][in][2] * scale;
            float v3 = acc[im][in][3] * scale;
            if (OUTH) {
                if (epi == 2) {   // SwiGLU: C = silu(Res) * acc
                    float2 r0 = *(const float2*)&Res[(size_t)(r  )*ldc + c];
                    float2 r1 = *(const float2*)&Res[(size_t)(r+8)*ldc + c];
                    v0 *= r0.x / (1.f + __expf(-r0.x));
                    v1 *= r0.y / (1.f + __expf(-r0.y));
                    v2 *= r1.x / (1.f + __expf(-r1.x));
                    v3 *= r1.y / (1.f + __expf(-r1.y));
                }
                __half* C = (__half*)Cv + coff;
                *(__half2*)&C[(size_t)(r  )*ldc + c] = __floats2half2_rn(v0, v1);
                *(__half2*)&C[(size_t)(r+8)*ldc + c] = __floats2half2_rn(v2, v3);
            } else {
                float* C = (float*)Cv + coff;
                float2 t0 = {v0, v1}, t1 = {v2, v3};
                if (epi == 1) {
                    float2 r0 = *(const float2*)&Res[(size_t)(r  )*ldc + c];
                    float2 r1 = *(const float2*)&Res[(size_t)(r+8)*ldc + c];
                    t0.x += r0.x; t0.y += r0.y;
                    t1.x += r1.x; t1.y += r1.y;
                }
                *(float2*)&C[(size_t)(r  )*ldc + c] = t0;
                *(float2*)&C[(size_t)(r+8)*ldc + c] = t1;
            }
        }
    }
}

// ---------------- merged weight conversion f32 -> f16 ----------------
#define S4 (DM*DM/4)
#define L4 (DFF*DM/4)
__global__ __launch_bounds__(256)
void cvt_all_kernel(const float* __restrict__ wq, const float* __restrict__ wk,
                    const float* __restrict__ wv, const float* __restrict__ wo,
                    const float* __restrict__ wg, const float* __restrict__ wu,
                    const float* __restrict__ wd,
                    __half* __restrict__ oq, __half* __restrict__ ok,
                    __half* __restrict__ ov, __half* __restrict__ oo,
                    __half* __restrict__ og, __half* __restrict__ ou,
                    __half* __restrict__ od)
{
    int i = blockIdx.x * 256 + threadIdx.x;
    const float* src; __half* dst; int off;
    if (i < 4*S4) {
        int w = i / S4; off = i - w*S4;
        src = (w == 0) ? wq : (w == 1) ? wk : (w == 2) ? wv : wo;
        dst = (w == 0) ? oq : (w == 1) ? ok : (w == 2) ? ov : oo;
    } else {
        int j = i - 4*S4;
        int w = j / L4; off = j - w*L4;
        src = (w == 0) ? wg : (w == 1) ? wu : wd;
        dst = (w == 0) ? og : (w == 1) ? ou : od;
    }
    float4 v = ((const float4*)src)[off];
    ((__half2*)dst)[2*off    ] = __floats2half2_rn(v.x, v.y);
    ((__half2*)dst)[2*off + 1] = __floats2half2_rn(v.z, v.w);
}

// ---------------- LayerNorm (half output) ----------------
__global__ __launch_bounds__(256)
void ln_kernel(const float* __restrict__ x, const float* __restrict__ w,
               const float* __restrict__ b, __half* __restrict__ y)
{
    const int row = blockIdx.x;
    const float* xr = x + (size_t)row * DM;
    __half*      yr = y + (size_t)row * DM;

    float s = 0.f, sq = 0.f;
#pragma unroll
    for (int i = 0; i < DM/256; i++) {
        float v = xr[threadIdx.x + i*256];
        s += v; sq += v*v;
    }
#pragma unroll
    for (int o = 16; o; o >>= 1) {
        s  += __shfl_xor_sync(0xffffffffu, s,  o);
        sq += __shfl_xor_sync(0xffffffffu, sq, o);
    }
    __shared__ float sh[64];
    const int warp = threadIdx.x >> 5, lane = threadIdx.x & 31;
    if (lane == 0) { sh[warp] = s; sh[warp + 32] = sq; }
    __syncthreads();
    if (warp == 0) {
        s  = (lane < 8) ? sh[lane]      : 0.f;
        sq = (lane < 8) ? sh[lane + 32] : 0.f;
#pragma unroll
        for (int o = 4; o; o >>= 1) {
            s  += __shfl_xor_sync(0xffffffffu, s,  o);
            sq += __shfl_xor_sync(0xffffffffu, sq, o);
        }
        if (lane == 0) { sh[0] = s; sh[1] = sq; }
    }
    __syncthreads();
    const float mean = sh[0] * (1.f/DM);
    const float var  = sh[1] * (1.f/DM) - mean*mean;
    const float inv  = rsqrtf(var + 1e-5f);
#pragma unroll
    for (int i = 0; i < DM/256; i++) {
        int c = threadIdx.x + i*256;
        yr[c] = __float2half_rn((xr[c] - mean) * inv * w[c] + b[c]);
    }
}

// ---------------- softmax: fp32 scores -> fp16 probs ----------------
__global__ __launch_bounds__(256)
void softmax_kernel(const float* __restrict__ s, __half* __restrict__ p)
{
    const float* r = s + (size_t)blockIdx.x * TT;
    __half*      o = p + (size_t)blockIdx.x * TT;
    float v[TT/256];
    float mx = -1e30f;
#pragma unroll
    for (int i = 0; i < TT/256; i++) {
        v[i] = r[threadIdx.x + i*256];
        mx = fmaxf(mx, v[i]);
    }
#pragma unroll
    for (int ofs = 16; ofs; ofs >>= 1) mx = fmaxf(mx, __shfl_xor_sync(0xffffffffu, mx, ofs));
    __shared__ float sh[32];
    const int warp = threadIdx.x >> 5, lane = threadIdx.x & 31;
    if (lane == 0) sh[warp] = mx;
    __syncthreads();
    if (warp == 0) {
        mx = (lane < 8) ? sh[lane] : -1e30f;
#pragma unroll
        for (int ofs = 4; ofs; ofs >>= 1) mx = fmaxf(mx, __shfl_xor_sync(0xffffffffu, mx, ofs));
        if (lane == 0) sh[0] = mx;
    }
    __syncthreads();
    mx = sh[0];

    float sum = 0.f;
#pragma unroll
    for (int i = 0; i < TT/256; i++) { v[i] = __expf(v[i] - mx); sum += v[i]; }
#pragma unroll
    for (int ofs = 16; ofs; ofs >>= 1) sum += __shfl_xor_sync(0xffffffffu, sum, ofs);
    if (lane == 0) sh[warp] = sum;
    __syncthreads();
    if (warp == 0) {
        sum = (lane < 8) ? sh[lane] : 0.f;
#pragma unroll
        for (int ofs = 4; ofs; ofs >>= 1) sum += __shfl_xor_sync(0xffffffffu, sum, ofs);
        if (lane == 0) sh[0] = sum;
    }
    __syncthreads();
    const float inv = 1.f / sh[0];
#pragma unroll
    for (int i = 0; i < TT/256; i++)
        o[threadIdx.x + i*256] = __float2half_rn(v[i] * inv);
}

// ---------------- V -> V^T per batch (half) ----------------
__global__ void transpose_v_kernel(const __half* __restrict__ v, __half* __restrict__ vt)
{
    __shared__ __half tile[32][34];
    const int b  = blockIdx.z;
    const int x0 = blockIdx.x * 32;
    const int y0 = blockIdx.y * 32;
    const __half* vb = v  + (size_t)b * TT * DM;
    __half*      vtb = vt + (size_t)b * TT * DM;
    const int tx = threadIdx.x, ty = threadIdx.y;
#pragma unroll
    for (int i = 0; i < 32; i += 8)
        tile[ty + i][tx] = vb[(size_t)(y0 + ty + i) * DM + x0 + tx];
    __syncthreads();
#pragma unroll
    for (int i = 0; i < 32; i += 8)
        vtb[(size_t)(x0 + ty + i) * TT + y0 + tx] = tile[tx][ty + i];
}

// ---------------- launch ----------------
extern "C" void kernel_launch(void* const* d_in, const int* in_sizes, int n_in,
                              void* d_out, int out_size)
{
    const float* x     = (const float*)d_in[0];
    const float* wq    = (const float*)d_in[1];
    const float* wk    = (const float*)d_in[2];
    const float* wv    = (const float*)d_in[3];
    const float* wo    = (const float*)d_in[4];
    const float* wg    = (const float*)d_in[5];
    const float* wu    = (const float*)d_in[6];
    const float* wd    = (const float*)d_in[7];
    const float* ln1w  = (const float*)d_in[8];
    const float* ln1b  = (const float*)d_in[9];
    const float* ln2w  = (const float*)d_in[10];
    const float* ln2b  = (const float*)d_in[11];
    float* out = (float*)d_out;

    __half *h1, *q, *k, *v, *vt, *scp, *attn, *h2, *ff;
    float  *sc, *x1, *gate;
    __half *rwq, *rwk, *rwv, *rwo, *rwg, *rwu, *rwd;
    cudaGetSymbolAddress((void**)&h1,   g_h1);
    cudaGetSymbolAddress((void**)&q,    g_q);
    cudaGetSymbolAddress((void**)&k,    g_k);
    cudaGetSymbolAddress((void**)&v,    g_v);
    cudaGetSymbolAddress((void**)&vt,   g_vT);
    cudaGetSymbolAddress((void**)&sc,   g_sc);
    cudaGetSymbolAddress((void**)&scp,  g_scp);
    cudaGetSymbolAddress((void**)&attn, g_attn);
    cudaGetSymbolAddress((void**)&x1,   g_x1);
    cudaGetSymbolAddress((void**)&h2,   g_h2);
    cudaGetSymbolAddress((void**)&gate, g_gate);
    cudaGetSymbolAddress((void**)&ff,   g_ff);
    cudaGetSymbolAddress((void**)&rwq,  g_wq);
    cudaGetSymbolAddress((void**)&rwk,  g_wk);
    cudaGetSymbolAddress((void**)&rwv,  g_wv);
    cudaGetSymbolAddress((void**)&rwo,  g_wo);
    cudaGetSymbolAddress((void**)&rwg,  g_wg);
    cudaGetSymbolAddress((void**)&rwu,  g_wu);
    cudaGetSymbolAddress((void**)&rwd,  g_wd);

    cudaFuncSetAttribute(gemm_f16<0>, cudaFuncAttributeMaxDynamicSharedMemorySize, GEMM_SMEM_BYTES);
    cudaFuncSetAttribute(gemm_f16<1>, cudaFuncAttributeMaxDynamicSharedMemorySize, GEMM_SMEM_BYTES);

    const long long LTTDM = (long long)TT * DM;
    const long long LTTTT = (long long)TT * TT;

    // 0. convert all weights to fp16 (single launch)
    {
        int total = 4*S4 + 3*L4;
        cvt_all_kernel<<<total/256, 256>>>(wq, wk, wv, wo, wg, wu, wd,
                                           rwq, rwk, rwv, rwo, rwg, rwu, rwd);
    }

    // 1. h1 = half(LN1(x))
    ln_kernel<<<TOK, 256>>>(x, ln1w, ln1b, h1);

    // 2-4. Q, K, V projections (half outputs)
    {
        dim3 grid(DM/BN, TOK/BM, 1);
        gemm_f16<1><<<grid, 256, GEMM_SMEM_BYTES>>>(h1, rwq, q, nullptr, DM, DM, DM, DM,
                                        0,0, 0,0, 0,0, 1, 1.f, 0);
        gemm_f16<1><<<grid, 256, GEMM_SMEM_BYTES>>>(h1, rwk, k, nullptr, DM, DM, DM, DM,
                                        0,0, 0,0, 0,0, 1, 1.f, 0);
        gemm_f16<1><<<grid, 256, GEMM_SMEM_BYTES>>>(h1, rwv, v, nullptr, DM, DM, DM, DM,
                                        0,0, 0,0, 0,0, 1, 1.f, 0);
    }

    // 5. V^T per batch
    {
        dim3 grid(DM/32, TT/32, NB);
        dim3 blk(32, 8);
        transpose_v_kernel<<<grid, blk>>>(v, vt);
    }

    // 6. scores = Q @ K^T / sqrt(HD)  (fp32 out), z = b*16+h
    {
        dim3 grid(TT/BN, TT/BM, NB*NH);
        gemm_f16<0><<<grid, 256, GEMM_SMEM_BYTES>>>(q, k, sc, nullptr, HD, DM, DM, TT,
                                        (long long)HD, LTTDM,
                                        (long long)HD, LTTDM,
                                        LTTTT, 16*LTTTT,
                                        NH, 0.08838834764831845f, 0);
    }

    // 7. softmax -> half probs
    softmax_kernel<<<NB*NH*TT, 256>>>(sc, scp);

    // 8. attn = P @ V (half out)
    {
        dim3 grid(HD/BN, TT/BM, NB*NH);
        gemm_f16<1><<<grid, 256, GEMM_SMEM_BYTES>>>(scp, vt, attn, nullptr, TT, TT, TT, DM,
                                        LTTTT, 16*LTTTT,
                                        (long long)HD*TT, LTTDM,
                                        (long long)HD, LTTDM,
                                        NH, 1.f, 0);
    }

    // 9. x1 = x + attn @ wo^T (fp32 out + residual)
    {
        dim3 grid(DM/BN, TOK/BM, 1);
        gemm_f16<0><<<grid, 256, GEMM_SMEM_BYTES>>>(attn, rwo, x1, x, DM, DM, DM, DM,
                                        0,0, 0,0, 0,0, 1, 1.f, 1);
    }

    // 10. h2 = half(LN2(x1))
    ln_kernel<<<TOK, 256>>>(x1, ln2w, ln2b, h2);

    // 11. gate (fp32 out)
    {
        dim3 grid(DFF/BN, TOK/BM, 1);
        gemm_f16<0><<<grid, 256, GEMM_SMEM_BYTES>>>(h2, rwg, gate, nullptr, DM, DM, DM, DFF,
                                        0,0, 0,0, 0,0, 1, 1.f, 0);
        // 12. up + fused SwiGLU: ff = half(silu(gate) * up)
        gemm_f16<1><<<grid, 256, GEMM_SMEM_BYTES>>>(h2, rwu, ff, gate, DM, DM, DM, DFF,
                                        0,0, 0,0, 0,0, 1, 1.f, 2);
    }

    // 13. out = x1 + ff @ wd^T (fp32 out + residual)
    {
        dim3 grid(DM/BN, TOK/BM, 1);
        gemm_f16<0><<<grid, 256, GEMM_SMEM_BYTES>>>(ff, rwd, out, x1, DFF, DFF, DFF, DM,
                                        0,0, 0,0, 0,0, 1, 1.f, 1);
    }
}

// round 15
// speedup vs baseline: 2.0220x; 1.0435x over previous
#include <cuda_runtime.h>
#include <cuda_fp16.h>
#include <stdint.h>

// ---------------- problem constants ----------------
#define NB   2
#define TT   2048
#define DM   2048
#define NH   16
#define HD   128
#define DFF  8192
#define TOK  (NB*TT)

// ---------------- scratch (device globals) ----------------
__device__ __half g_h1  [(size_t)TOK*DM];
__device__ __half g_q   [(size_t)TOK*DM];
__device__ __half g_k   [(size_t)TOK*DM];
__device__ __half g_v   [(size_t)TOK*DM];
__device__ __half g_vT  [(size_t)TOK*DM];
__device__ float  g_sc  [(size_t)NB*NH*TT*TT];   // fp32 scores
__device__ __half g_scp [(size_t)NB*NH*TT*TT];   // fp16 probs
__device__ __half g_attn[(size_t)TOK*DM];
__device__ float  g_x1  [(size_t)TOK*DM];
__device__ __half g_h2  [(size_t)TOK*DM];
__device__ float  g_gate[(size_t)TOK*DFF];
__device__ __half g_ff  [(size_t)TOK*DFF];
__device__ __half g_wq[(size_t)DM*DM];
__device__ __half g_wk[(size_t)DM*DM];
__device__ __half g_wv[(size_t)DM*DM];
__device__ __half g_wo[(size_t)DM*DM];
__device__ __half g_wg[(size_t)DFF*DM];
__device__ __half g_wu[(size_t)DFF*DM];
__device__ __half g_wd[(size_t)DM*DFF];

// ---------------- helpers ----------------
__device__ __forceinline__ void cpasync16(void* dst, const void* src) {
    uint32_t s = (uint32_t)__cvta_generic_to_shared(dst);
    asm volatile("cp.async.cg.shared.global [%0], [%1], 16;\n" :: "r"(s), "l"(src));
}

__device__ __forceinline__ void ldsm_x4(uint32_t& r0, uint32_t& r1,
                                        uint32_t& r2, uint32_t& r3, uint32_t addr) {
    asm volatile("ldmatrix.sync.aligned.m8n8.x4.shared.b16 {%0,%1,%2,%3}, [%4];"
                 : "=r"(r0), "=r"(r1), "=r"(r2), "=r"(r3) : "r"(addr));
}

// ---------------- fp16 tensor-core GEMM ----------------
// 128x64 CTA tile, 128 threads (4 warps, each 32(M)x64(N)), 4 CTAs/SM.
// C[m,n] = scale * sum_k A[m,k]*B[n,k]
// epi=1 (OUTH=0): += Res.   epi=2 (OUTH=1): C = silu(Res) * acc  (SwiGLU fuse)
#define BM  128
#define BN  64
#define BK  32
#define SROW 40                     // halves per smem row (32 + 8 pad)
#define ASTG_A (BM*SROW)            // 5120 halves
#define ASTG_B (BN*SROW)            // 2560 halves
#define STG_H  (ASTG_A + ASTG_B)    // 7680 halves per stage
#define NSTAGE 3
#define GEMM_SMEM_BYTES (NSTAGE*STG_H*2)   // 46,080 B

extern __shared__ __half s16[];

template<int OUTH>
__global__ __launch_bounds__(128, 4)
void gemm_f16(const __half* __restrict__ A, const __half* __restrict__ Bm,
              void* __restrict__ Cv, const float* __restrict__ Res,
              int K, int lda, int ldb, int ldc,
              long long zaLo, long long zaHi,
              long long zbLo, long long zbHi,
              long long zcLo, long long zcHi,
              int zdiv, float scale, int epi)
{
    long long zq = blockIdx.z / zdiv, zr = blockIdx.z % zdiv;
    A  += zq*zaHi + zr*zaLo;
    Bm += zq*zbHi + zr*zbLo;
    const long long coff = zq*zcHi + zr*zcLo;
    if (epi) Res += coff;

    const int m0 = blockIdx.y * BM;
    const int n0 = blockIdx.x * BN;

    const int tid  = threadIdx.x;
    const int lane = tid & 31;
    const int warp = tid >> 5;      // 0..3
    const int mb   = warp * 32;     // warp tile 32(M) x 64(N), nb = 0

    float acc[2][8][4];
#pragma unroll
    for (int i = 0; i < 2; i++)
#pragma unroll
        for (int j = 0; j < 8; j++)
#pragma unroll
            for (int l = 0; l < 4; l++) acc[i][j][l] = 0.f;

    const int nK = K / BK;   // >= 4 for all shapes here

    // ldmatrix lane-address offsets (bytes) within a stage
    const uint32_t s16u = (uint32_t)__cvta_generic_to_shared(s16);
    const int lrow  = lane & 15;
    const int lchnk = (lane >> 4) * 8;
    const uint32_t aoff0 = (uint32_t)(((mb + lrow) * SROW + lchnk) * 2);
    const uint32_t aoff1 = aoff0 + 16 * SROW * 2;
    uint32_t boff[4];
#pragma unroll
    for (int p = 0; p < 4; p++)
        boff[p] = (uint32_t)(ASTG_A * 2 + ((p*16 + lrow) * SROW + lchnk) * 2);

    auto load_stage = [&](int st, int kt) {
        const int k0 = kt * BK;
        __half* sa = s16 + st * STG_H;
        __half* sb = sa + ASTG_A;
#pragma unroll
        for (int i = 0; i < 4; i++) {          // A: 128 rows x 4 chunks
            int idx = tid + i * 128;           // 0..511
            int row = idx >> 2;
            int c8  = (idx & 3) << 3;
            cpasync16(&sa[row*SROW + c8], A + (size_t)(m0+row)*lda + k0 + c8);
        }
#pragma unroll
        for (int i = 0; i < 2; i++) {          // B: 64 rows x 4 chunks
            int idx = tid + i * 128;           // 0..255
            int row = idx >> 2;
            int c8  = (idx & 3) << 3;
            cpasync16(&sb[row*SROW + c8], Bm + (size_t)(n0+row)*ldb + k0 + c8);
        }
    };

    auto compute = [&](int slot) {
        const uint32_t stg = s16u + (uint32_t)(slot * STG_H * 2);
#pragma unroll
        for (int kk = 0; kk < BK; kk += 16) {
            const uint32_t kb = stg + kk * 2;
            uint32_t af[2][4];
            ldsm_x4(af[0][0], af[0][1], af[0][2], af[0][3], kb + aoff0);
            ldsm_x4(af[1][0], af[1][1], af[1][2], af[1][3], kb + aoff1);
            uint32_t bf[8][2];
#pragma unroll
            for (int p = 0; p < 4; p++) {
                ldsm_x4(bf[2*p][0], bf[2*p+1][0], bf[2*p][1], bf[2*p+1][1], kb + boff[p]);
            }
#pragma unroll
            for (int im = 0; im < 2; im++)
#pragma unroll
                for (int in = 0; in < 8; in++) {
                    asm volatile(
                        "mma.sync.aligned.m16n8k16.row.col.f32.f16.f16.f32 "
                        "{%0,%1,%2,%3}, {%4,%5,%6,%7}, {%8,%9}, {%0,%1,%2,%3};\n"
                        : "+f"(acc[im][in][0]), "+f"(acc[im][in][1]),
                          "+f"(acc[im][in][2]), "+f"(acc[im][in][3])
                        : "r"(af[im][0]), "r"(af[im][1]),
                          "r"(af[im][2]), "r"(af[im][3]),
                          "r"(bf[in][0]), "r"(bf[in][1]));
                }
        }
    };

    // prologue: 2 stages in flight (prefetch distance 2 <= NSTAGE-1)
    load_stage(0, 0);
    asm volatile("cp.async.commit_group;\n");
    load_stage(1, 1);
    asm volatile("cp.async.commit_group;\n");

    for (int kt = 0; kt < nK; kt++) {
        // retire stage kt's copy group (per-thread) ...
        if (kt + 1 < nK) asm volatile("cp.async.wait_group 1;\n");
        else             asm volatile("cp.async.wait_group 0;\n");
        // ... publish to all warps; also retires every warp's reads of slot (kt-1)%3
        __syncthreads();

        if (kt + 2 < nK) {
            load_stage((kt + 2) % NSTAGE, kt + 2);   // targets slot (kt-1)%3: safe
            asm volatile("cp.async.commit_group;\n");
        }

        compute(kt % NSTAGE);
    }

    // epilogue
#pragma unroll
    for (int im = 0; im < 2; im++) {
#pragma unroll
        for (int in = 0; in < 8; in++) {
            int r = m0 + mb + im*16 + (lane >> 2);
            int c = n0 + in*8 + ((lane & 3) << 1);
            float v0 = acc[im][in][0] * scale;
            float v1 = acc[im][in][1] * scale;
            float v2 = acc[im][in][2] * scale;
            float v3 = acc[im][in][3] * scale;
            if (OUTH) {
                if (epi == 2) {   // SwiGLU: C = silu(Res) * acc
                    float2 r0 = *(const float2*)&Res[(size_t)(r  )*ldc + c];
                    float2 r1 = *(const float2*)&Res[(size_t)(r+8)*ldc + c];
                    v0 *= r0.x / (1.f + __expf(-r0.x));
                    v1 *= r0.y / (1.f + __expf(-r0.y));
                    v2 *= r1.x / (1.f + __expf(-r1.x));
                    v3 *= r1.y / (1.f + __expf(-r1.y));
                }
                __half* C = (__half*)Cv + coff;
                *(__half2*)&C[(size_t)(r  )*ldc + c] = __floats2half2_rn(v0, v1);
                *(__half2*)&C[(size_t)(r+8)*ldc + c] = __floats2half2_rn(v2, v3);
            } else {
                float* C = (float*)Cv + coff;
                float2 t0 = {v0, v1}, t1 = {v2, v3};
                if (epi == 1) {
                    float2 r0 = *(const float2*)&Res[(size_t)(r  )*ldc + c];
                    float2 r1 = *(const float2*)&Res[(size_t)(r+8)*ldc + c];
                    t0.x += r0.x; t0.y += r0.y;
                    t1.x += r1.x; t1.y += r1.y;
                }
                *(float2*)&C[(size_t)(r  )*ldc + c] = t0;
                *(float2*)&C[(size_t)(r+8)*ldc + c] = t1;
            }
        }
    }
}

// ---------------- merged weight conversion f32 -> f16 ----------------
#define S4 (DM*DM/4)
#define L4 (DFF*DM/4)
__global__ __launch_bounds__(256)
void cvt_all_kernel(const float* __restrict__ wq, const float* __restrict__ wk,
                    const float* __restrict__ wv, const float* __restrict__ wo,
                    const float* __restrict__ wg, const float* __restrict__ wu,
                    const float* __restrict__ wd,
                    __half* __restrict__ oq, __half* __restrict__ ok,
                    __half* __restrict__ ov, __half* __restrict__ oo,
                    __half* __restrict__ og, __half* __restrict__ ou,
                    __half* __restrict__ od)
{
    int i = blockIdx.x * 256 + threadIdx.x;
    const float* src; __half* dst; int off;
    if (i < 4*S4) {
        int w = i / S4; off = i - w*S4;
        src = (w == 0) ? wq : (w == 1) ? wk : (w == 2) ? wv : wo;
        dst = (w == 0) ? oq : (w == 1) ? ok : (w == 2) ? ov : oo;
    } else {
        int j = i - 4*S4;
        int w = j / L4; off = j - w*L4;
        src = (w == 0) ? wg : (w == 1) ? wu : wd;
        dst = (w == 0) ? og : (w == 1) ? ou : od;
    }
    float4 v = ((const float4*)src)[off];
    ((__half2*)dst)[2*off    ] = __floats2half2_rn(v.x, v.y);
    ((__half2*)dst)[2*off + 1] = __floats2half2_rn(v.z, v.w);
}

// ---------------- LayerNorm (half output) ----------------
__global__ __launch_bounds__(256)
void ln_kernel(const float* __restrict__ x, const float* __restrict__ w,
               const float* __restrict__ b, __half* __restrict__ y)
{
    const int row = blockIdx.x;
    const float* xr = x + (size_t)row * DM;
    __half*      yr = y + (size_t)row * DM;

    float s = 0.f, sq = 0.f;
#pragma unroll
    for (int i = 0; i < DM/256; i++) {
        float v = xr[threadIdx.x + i*256];
        s += v; sq += v*v;
    }
#pragma unroll
    for (int o = 16; o; o >>= 1) {
        s  += __shfl_xor_sync(0xffffffffu, s,  o);
        sq += __shfl_xor_sync(0xffffffffu, sq, o);
    }
    __shared__ float sh[64];
    const int warp = threadIdx.x >> 5, lane = threadIdx.x & 31;
    if (lane == 0) { sh[warp] = s; sh[warp + 32] = sq; }
    __syncthreads();
    if (warp == 0) {
        s  = (lane < 8) ? sh[lane]      : 0.f;
        sq = (lane < 8) ? sh[lane + 32] : 0.f;
#pragma unroll
        for (int o = 4; o; o >>= 1) {
            s  += __shfl_xor_sync(0xffffffffu, s,  o);
            sq += __shfl_xor_sync(0xffffffffu, sq, o);
        }
        if (lane == 0) { sh[0] = s; sh[1] = sq; }
    }
    __syncthreads();
    const float mean = sh[0] * (1.f/DM);
    const float var  = sh[1] * (1.f/DM) - mean*mean;
    const float inv  = rsqrtf(var + 1e-5f);
#pragma unroll
    for (int i = 0; i < DM/256; i++) {
        int c = threadIdx.x + i*256;
        yr[c] = __float2half_rn((xr[c] - mean) * inv * w[c] + b[c]);
    }
}

// ---------------- softmax: fp32 scores -> fp16 probs ----------------
__global__ __launch_bounds__(256)
void softmax_kernel(const float* __restrict__ s, __half* __restrict__ p)
{
    const float* r = s + (size_t)blockIdx.x * TT;
    __half*      o = p + (size_t)blockIdx.x * TT;
    float v[TT/256];
    float mx = -1e30f;
#pragma unroll
    for (int i = 0; i < TT/256; i++) {
        v[i] = r[threadIdx.x + i*256];
        mx = fmaxf(mx, v[i]);
    }
#pragma unroll
    for (int ofs = 16; ofs; ofs >>= 1) mx = fmaxf(mx, __shfl_xor_sync(0xffffffffu, mx, ofs));
    __shared__ float sh[32];
    const int warp = threadIdx.x >> 5, lane = threadIdx.x & 31;
    if (lane == 0) sh[warp] = mx;
    __syncthreads();
    if (warp == 0) {
        mx = (lane < 8) ? sh[lane] : -1e30f;
#pragma unroll
        for (int ofs = 4; ofs; ofs >>= 1) mx = fmaxf(mx, __shfl_xor_sync(0xffffffffu, mx, ofs));
        if (lane == 0) sh[0] = mx;
    }
    __syncthreads();
    mx = sh[0];

    float sum = 0.f;
#pragma unroll
    for (int i = 0; i < TT/256; i++) { v[i] = __expf(v[i] - mx); sum += v[i]; }
#pragma unroll
    for (int ofs = 16; ofs; ofs >>= 1) sum += __shfl_xor_sync(0xffffffffu, sum, ofs);
    if (lane == 0) sh[warp] = sum;
    __syncthreads();
    if (warp == 0) {
        sum = (lane < 8) ? sh[lane] : 0.f;
#pragma unroll
        for (int ofs = 4; ofs; ofs >>= 1) sum += __shfl_xor_sync(0xffffffffu, sum, ofs);
        if (lane == 0) sh[0] = sum;
    }
    __syncthreads();
    const float inv = 1.f / sh[0];
#pragma unroll
    for (int i = 0; i < TT/256; i++)
        o[threadIdx.x + i*256] = __float2half_rn(v[i] * inv);
}

// ---------------- V -> V^T per batch (half) ----------------
__global__ void transpose_v_kernel(const __half* __restrict__ v, __half* __restrict__ vt)
{
    __shared__ __half tile[32][34];
    const int b  = blockIdx.z;
    const int x0 = blockIdx.x * 32;
    const int y0 = blockIdx.y * 32;
    const __half* vb = v  + (size_t)b * TT * DM;
    __half*      vtb = vt + (size_t)b * TT * DM;
    const int tx = threadIdx.x, ty = threadIdx.y;
#pragma unroll
    for (int i = 0; i < 32; i += 8)
        tile[ty + i][tx] = vb[(size_t)(y0 + ty + i) * DM + x0 + tx];
    __syncthreads();
#pragma unroll
    for (int i = 0; i < 32; i += 8)
        vtb[(size_t)(x0 + ty + i) * TT + y0 + tx] = tile[tx][ty + i];
}

// ---------------- launch ----------------
extern "C" void kernel_launch(void* const* d_in, const int* in_sizes, int n_in,
                              void* d_out, int out_size)
{
    const float* x     = (const float*)d_in[0];
    const float* wq    = (const float*)d_in[1];
    const float* wk    = (const float*)d_in[2];
    const float* wv    = (const float*)d_in[3];
    const float* wo    = (const float*)d_in[4];
    const float* wg    = (const float*)d_in[5];
    const float* wu    = (const float*)d_in[6];
    const float* wd    = (const float*)d_in[7];
    const float* ln1w  = (const float*)d_in[8];
    const float* ln1b  = (const float*)d_in[9];
    const float* ln2w  = (const float*)d_in[10];
    const float* ln2b  = (const float*)d_in[11];
    float* out = (float*)d_out;

    __half *h1, *q, *k, *v, *vt, *scp, *attn, *h2, *ff;
    float  *sc, *x1, *gate;
    __half *rwq, *rwk, *rwv, *rwo, *rwg, *rwu, *rwd;
    cudaGetSymbolAddress((void**)&h1,   g_h1);
    cudaGetSymbolAddress((void**)&q,    g_q);
    cudaGetSymbolAddress((void**)&k,    g_k);
    cudaGetSymbolAddress((void**)&v,    g_v);
    cudaGetSymbolAddress((void**)&vt,   g_vT);
    cudaGetSymbolAddress((void**)&sc,   g_sc);
    cudaGetSymbolAddress((void**)&scp,  g_scp);
    cudaGetSymbolAddress((void**)&attn, g_attn);
    cudaGetSymbolAddress((void**)&x1,   g_x1);
    cudaGetSymbolAddress((void**)&h2,   g_h2);
    cudaGetSymbolAddress((void**)&gate, g_gate);
    cudaGetSymbolAddress((void**)&ff,   g_ff);
    cudaGetSymbolAddress((void**)&rwq,  g_wq);
    cudaGetSymbolAddress((void**)&rwk,  g_wk);
    cudaGetSymbolAddress((void**)&rwv,  g_wv);
    cudaGetSymbolAddress((void**)&rwo,  g_wo);
    cudaGetSymbolAddress((void**)&rwg,  g_wg);
    cudaGetSymbolAddress((void**)&rwu,  g_wu);
    cudaGetSymbolAddress((void**)&rwd,  g_wd);

    cudaFuncSetAttribute(gemm_f16<0>, cudaFuncAttributeMaxDynamicSharedMemorySize, GEMM_SMEM_BYTES);
    cudaFuncSetAttribute(gemm_f16<1>, cudaFuncAttributeMaxDynamicSharedMemorySize, GEMM_SMEM_BYTES);

    const long long LTTDM = (long long)TT * DM;
    const long long LTTTT = (long long)TT * TT;

    // 0. convert all weights to fp16 (single launch)
    {
        int total = 4*S4 + 3*L4;
        cvt_all_kernel<<<total/256, 256>>>(wq, wk, wv, wo, wg, wu, wd,
                                           rwq, rwk, rwv, rwo, rwg, rwu, rwd);
    }

    // 1. h1 = half(LN1(x))
    ln_kernel<<<TOK, 256>>>(x, ln1w, ln1b, h1);

    // 2-4. Q, K, V projections (half outputs)
    {
        dim3 grid(DM/BN, TOK/BM, 1);
        gemm_f16<1><<<grid, 128, GEMM_SMEM_BYTES>>>(h1, rwq, q, nullptr, DM, DM, DM, DM,
                                        0,0, 0,0, 0,0, 1, 1.f, 0);
        gemm_f16<1><<<grid, 128, GEMM_SMEM_BYTES>>>(h1, rwk, k, nullptr, DM, DM, DM, DM,
                                        0,0, 0,0, 0,0, 1, 1.f, 0);
        gemm_f16<1><<<grid, 128, GEMM_SMEM_BYTES>>>(h1, rwv, v, nullptr, DM, DM, DM, DM,
                                        0,0, 0,0, 0,0, 1, 1.f, 0);
    }

    // 5. V^T per batch
    {
        dim3 grid(DM/32, TT/32, NB);
        dim3 blk(32, 8);
        transpose_v_kernel<<<grid, blk>>>(v, vt);
    }

    // 6. scores = Q @ K^T / sqrt(HD)  (fp32 out), z = b*16+h
    {
        dim3 grid(TT/BN, TT/BM, NB*NH);
        gemm_f16<0><<<grid, 128, GEMM_SMEM_BYTES>>>(q, k, sc, nullptr, HD, DM, DM, TT,
                                        (long long)HD, LTTDM,
                                        (long long)HD, LTTDM,
                                        LTTTT, 16*LTTTT,
                                        NH, 0.08838834764831845f, 0);
    }

    // 7. softmax -> half probs
    softmax_kernel<<<NB*NH*TT, 256>>>(sc, scp);

    // 8. attn = P @ V (half out)
    {
        dim3 grid(HD/BN, TT/BM, NB*NH);
        gemm_f16<1><<<grid, 128, GEMM_SMEM_BYTES>>>(scp, vt, attn, nullptr, TT, TT, TT, DM,
                                        LTTTT, 16*LTTTT,
                                        (long long)HD*TT, LTTDM,
                                        (long long)HD, LTTDM,
                                        NH, 1.f, 0);
    }

    // 9. x1 = x + attn @ wo^T (fp32 out + residual)
    {
        dim3 grid(DM/BN, TOK/BM, 1);
        gemm_f16<0><<<grid, 128, GEMM_SMEM_BYTES>>>(attn, rwo, x1, x, DM, DM, DM, DM,
                                        0,0, 0,0, 0,0, 1, 1.f, 1);
    }

    // 10. h2 = half(LN2(x1))
    ln_kernel<<<TOK, 256>>>(x1, ln2w, ln2b, h2);

    // 11. gate (fp32 out)
    {
        dim3 grid(DFF/BN, TOK/BM, 1);
        gemm_f16<0><<<grid, 128, GEMM_SMEM_BYTES>>>(h2, rwg, gate, nullptr, DM, DM, DM, DFF,
                                        0,0, 0,0, 0,0, 1, 1.f, 0);
        // 12. up + fused SwiGLU: ff = half(silu(gate) * up)
        gemm_f16<1><<<grid, 128, GEMM_SMEM_BYTES>>>(h2, rwu, ff, gate, DM, DM, DM, DFF,
                                        0,0, 0,0, 0,0, 1, 1.f, 2);
    }

    // 13. out = x1 + ff @ wd^T (fp32 out + residual)
    {
        dim3 grid(DM/BN, TOK/BM, 1);
        gemm_f16<0><<<grid, 128, GEMM_SMEM_BYTES>>>(ff, rwd, out, x1, DFF, DFF, DFF, DM,
                                        0,0, 0,0, 0,0, 1, 1.f, 1);
    }
}